// round 13
// baseline (speedup 1.0000x reference)
#include <cuda_runtime.h>
#include <cuda_bf16.h>
#include <cstdint>
#include <cstddef>
#include <math.h>

#define NN 1024
#define LL 2048
#define HH 128

// ---------------- scratch (device globals; no allocation) ----------------
static __device__ float g_k[(size_t)NN * LL * HH];   // 1 GiB
static __device__ float g_logits[(size_t)NN * LL];
static __device__ float g_x[NN * HH];
static __device__ float g_state[NN * HH];
static __device__ float g_q[NN * HH];
// Wk pre-paired: g_Wp[h2*128 + o] = (Wk[o][2*h2], Wk[o][2*h2+1]) as u64
static __device__ unsigned long long g_Wp[(HH / 2) * HH];

// ---------------- math helpers ----------------
__device__ __forceinline__ float ex2f(float x){ float r; asm("ex2.approx.f32 %0, %1;" : "=f"(r) : "f"(x)); return r; }
__device__ __forceinline__ float rcpaf(float x){ float r; asm("rcp.approx.f32 %0, %1;" : "=f"(r) : "f"(x)); return r; }

// tanh(x) = 1 - 2/(1+e^{2x}); ex2 + rcp + one Newton step  (~1e-7 abs err)
__device__ __forceinline__ float acc_tanh(float x){
    float y = fminf(x * 2.8853900817779268f, 80.0f);   // 2/ln(2)
    float e = ex2f(y);
    float d = e + 1.0f;
    float r = rcpaf(d);
    r = r * fmaf(-d, r, 2.0f);                         // Newton
    return fmaf(-2.0f, r, 1.0f);
}

#define FMA2(d, a, b) asm("fma.rn.f32x2 %0, %1, %2, %0;" : "+l"(d) : "l"(a), "l"(b))

__device__ __forceinline__ unsigned long long pack2(float lo, float hi){
    return (unsigned long long)__float_as_uint(lo)
         | ((unsigned long long)__float_as_uint(hi) << 32);
}
__device__ __forceinline__ float usum(unsigned long long a){
    return __uint_as_float((unsigned)(a & 0xffffffffULL))
         + __uint_as_float((unsigned)(a >> 32));
}

// ---------------- init decoder input to ones ----------------
__global__ void init_x_kernel(){
    int i = blockIdx.x * blockDim.x + threadIdx.x;
    if (i < NN * HH) g_x[i] = 1.0f;
}

// ---------------- build paired-weight layout (64 KB, once per replay) ----
__global__ void __launch_bounds__(HH) pair_wk_kernel(const float* __restrict__ Wk){
    const int h2 = blockIdx.x;      // 64 blocks
    const int o  = threadIdx.x;     // 128 threads
    g_Wp[h2 * HH + o] = pack2(Wk[o * HH + 2 * h2], Wk[o * HH + 2 * h2 + 1]);
}

// ---------------- GRU cell + q projection ----------------
#define GR 8
__global__ void __launch_bounds__(HH) gru_kernel(
    const float* __restrict__ x_in, const float* __restrict__ h_in,
    const float* __restrict__ W_ih, const float* __restrict__ W_hh,
    const float* __restrict__ b_ih, const float* __restrict__ b_hh,
    const float* __restrict__ Wq)
{
    __shared__ float x_s[GR][HH];
    __shared__ float h_s[GR][HH];
    __shared__ float hn_s[GR][HH];
    const int n0 = blockIdx.x * GR;
    const int j  = threadIdx.x;
    for (int r = 0; r < GR; r++){
        x_s[r][j] = x_in[(n0 + r) * HH + j];
        h_s[r][j] = h_in[(n0 + r) * HH + j];
    }
    __syncthreads();

    float ar[GR], az[GR], anx[GR], anh[GR];
    #pragma unroll
    for (int r = 0; r < GR; r++){ ar[r] = az[r] = anx[r] = anh[r] = 0.0f; }

    const float4* Wr = (const float4*)(W_ih + (size_t)j * HH);
    const float4* Wz = (const float4*)(W_ih + (size_t)(HH + j) * HH);
    const float4* Wn = (const float4*)(W_ih + (size_t)(2 * HH + j) * HH);
    const float4* Vr = (const float4*)(W_hh + (size_t)j * HH);
    const float4* Vz = (const float4*)(W_hh + (size_t)(HH + j) * HH);
    const float4* Vn = (const float4*)(W_hh + (size_t)(2 * HH + j) * HH);

    for (int h4 = 0; h4 < HH / 4; h4++){
        float4 wr = Wr[h4], wz = Wz[h4], wn = Wn[h4];
        float4 vr = Vr[h4], vz = Vz[h4], vn = Vn[h4];
        #pragma unroll
        for (int r = 0; r < GR; r++){
            float4 xx = *(const float4*)&x_s[r][h4 * 4];
            float4 hh = *(const float4*)&h_s[r][h4 * 4];
            ar[r]  += wr.x*xx.x + wr.y*xx.y + wr.z*xx.z + wr.w*xx.w
                    + vr.x*hh.x + vr.y*hh.y + vr.z*hh.z + vr.w*hh.w;
            az[r]  += wz.x*xx.x + wz.y*xx.y + wz.z*xx.z + wz.w*xx.w
                    + vz.x*hh.x + vz.y*hh.y + vz.z*hh.z + vz.w*hh.w;
            anx[r] += wn.x*xx.x + wn.y*xx.y + wn.z*xx.z + wn.w*xx.w;
            anh[r] += vn.x*hh.x + vn.y*hh.y + vn.z*hh.z + vn.w*hh.w;
        }
    }
    const float br  = b_ih[j] + b_hh[j];
    const float bz  = b_ih[HH + j] + b_hh[HH + j];
    const float bnx = b_ih[2 * HH + j];
    const float bnh = b_hh[2 * HH + j];
    #pragma unroll
    for (int r = 0; r < GR; r++){
        float rr = 1.0f / (1.0f + expf(-(ar[r] + br)));
        float zz = 1.0f / (1.0f + expf(-(az[r] + bz)));
        float nn = tanhf(anx[r] + bnx + rr * (anh[r] + bnh));
        float hp = (1.0f - zz) * nn + zz * h_s[r][j];
        hn_s[r][j] = hp;
        g_state[(n0 + r) * HH + j] = hp;
    }
    __syncthreads();
    float aq[GR];
    #pragma unroll
    for (int r = 0; r < GR; r++) aq[r] = 0.0f;
    const float4* Q = (const float4*)(Wq + (size_t)j * HH);
    for (int h4 = 0; h4 < HH / 4; h4++){
        float4 wq = Q[h4];
        #pragma unroll
        for (int r = 0; r < GR; r++){
            float4 hh = *(const float4*)&hn_s[r][h4 * 4];
            aq[r] += wq.x*hh.x + wq.y*hh.y + wq.z*hh.z + wq.w*hh.w;
        }
    }
    #pragma unroll
    for (int r = 0; r < GR; r++) g_q[(n0 + r) * HH + j] = aq[r];
}

// ---------------- fused k-GEMM + step-1 score ----------------
// grid (16, 1024): blockIdx.y = n, blockIdx.x = 128-row L-tile.
// 256 threads, 8 warps, 1 CTA/SM (64 KB smem + ~190 regs).
// Lane tile: O=8 outputs x R=8 rows (acc = 64 u64 packed even/odd-h sums).
// Warp w covers rows 16w..16w+15; half-warp hw (lane>>4) owns 8 rows;
// lane (lane&15) owns outputs o0 = 8*(lane&15) .. +7 (all 128 outputs per
// half-warp). Balance: per 4-h step, 16 x .128 loads (64 L1-cyc) vs
// 128 FFMA2 (64 FMA-cyc) -- both pipes ~balanced, 1.8x less L1 than R12.
__global__ void __launch_bounds__(256) kq_kernel(
    const float* __restrict__ eo,
    const float* __restrict__ w_score, const float* __restrict__ q)
{
    extern __shared__ float eo_s[];       // 128 x 128 floats = 64 KB
    const int n    = blockIdx.y;
    const int l0   = blockIdx.x * 128;
    const int w    = threadIdx.x >> 5;
    const int lane = threadIdx.x & 31;
    const int hw   = lane >> 4;           // half-warp: row sub-group
    const int ol   = lane & 15;           // output lane
    const int o0   = ol * 8;

    // stage eo tile: 4096 float4, 16 per thread, coalesced
    {
        const float4* src = (const float4*)(eo + ((size_t)n * LL + l0) * HH);
        float4* dst = (float4*)eo_s;
        #pragma unroll
        for (int it = 0; it < 16; it++)
            dst[threadIdx.x + it * 256] = src[threadIdx.x + it * 256];
    }
    __syncthreads();

    unsigned long long acc[8][8];         // [row][output] packed (even,odd)-h
    #pragma unroll
    for (int rr = 0; rr < 8; rr++)
        #pragma unroll
        for (int oi = 0; oi < 8; oi++) acc[rr][oi] = 0ULL;

    const unsigned long long* wp = g_Wp + o0;                 // + h2*HH
    const float* eo_b = eo_s + (w * 16 + hw * 8) * HH;

    #pragma unroll 1
    for (int h2 = 0; h2 < HH / 2; h2 += 2){
        // weights: outputs o0..o0+7 at h-pairs h2 (wa) and h2+1 (wb)
        ulonglong2 wa01 = *(const ulonglong2*)(wp + (size_t)h2 * HH);
        ulonglong2 wa23 = *(const ulonglong2*)(wp + (size_t)h2 * HH + 2);
        ulonglong2 wa45 = *(const ulonglong2*)(wp + (size_t)h2 * HH + 4);
        ulonglong2 wa67 = *(const ulonglong2*)(wp + (size_t)h2 * HH + 6);
        ulonglong2 wb01 = *(const ulonglong2*)(wp + (size_t)(h2 + 1) * HH);
        ulonglong2 wb23 = *(const ulonglong2*)(wp + (size_t)(h2 + 1) * HH + 2);
        ulonglong2 wb45 = *(const ulonglong2*)(wp + (size_t)(h2 + 1) * HH + 4);
        ulonglong2 wb67 = *(const ulonglong2*)(wp + (size_t)(h2 + 1) * HH + 6);
        #pragma unroll
        for (int rr = 0; rr < 8; rr++){
            // e.x = (eo[2h2], eo[2h2+1]), e.y = (eo[2h2+2], eo[2h2+3])
            ulonglong2 e = *(const ulonglong2*)(eo_b + rr * HH + 2 * h2);
            FMA2(acc[rr][0], wa01.x, e.x);  FMA2(acc[rr][0], wb01.x, e.y);
            FMA2(acc[rr][1], wa01.y, e.x);  FMA2(acc[rr][1], wb01.y, e.y);
            FMA2(acc[rr][2], wa23.x, e.x);  FMA2(acc[rr][2], wb23.x, e.y);
            FMA2(acc[rr][3], wa23.y, e.x);  FMA2(acc[rr][3], wb23.y, e.y);
            FMA2(acc[rr][4], wa45.x, e.x);  FMA2(acc[rr][4], wb45.x, e.y);
            FMA2(acc[rr][5], wa45.y, e.x);  FMA2(acc[rr][5], wb45.y, e.y);
            FMA2(acc[rr][6], wa67.x, e.x);  FMA2(acc[rr][6], wb67.x, e.y);
            FMA2(acc[rr][7], wa67.y, e.x);  FMA2(acc[rr][7], wb67.y, e.y);
        }
    }

    const float4 qv0 = *(const float4*)(q + (size_t)n * HH + o0);
    const float4 qv1 = *(const float4*)(q + (size_t)n * HH + o0 + 4);
    const float4 wv0 = *(const float4*)(w_score + o0);
    const float4 wv1 = *(const float4*)(w_score + o0 + 4);
    const int lr0 = l0 + w * 16 + hw * 8;

    #pragma unroll
    for (int rr = 0; rr < 8; rr++){
        const int l = lr0 + rr;
        float kv[8];
        #pragma unroll
        for (int oi = 0; oi < 8; oi++) kv[oi] = usum(acc[rr][oi]);
        float* kout = g_k + ((size_t)n * LL + l) * HH + o0;
        *(float4*)(kout)     = make_float4(kv[0], kv[1], kv[2], kv[3]);
        *(float4*)(kout + 4) = make_float4(kv[4], kv[5], kv[6], kv[7]);

        float s = wv0.x * acc_tanh(qv0.x + kv[0])
                + wv0.y * acc_tanh(qv0.y + kv[1])
                + wv0.z * acc_tanh(qv0.z + kv[2])
                + wv0.w * acc_tanh(qv0.w + kv[3])
                + wv1.x * acc_tanh(qv1.x + kv[4])
                + wv1.y * acc_tanh(qv1.y + kv[5])
                + wv1.z * acc_tanh(qv1.z + kv[6])
                + wv1.w * acc_tanh(qv1.w + kv[7]);
        // reduce across the 16 output-lanes (stays within half-warp)
        #pragma unroll
        for (int off = 8; off > 0; off >>= 1)
            s += __shfl_xor_sync(0xffffffffu, s, off);
        if (ol == 0) g_logits[(size_t)n * LL + l] = s;
    }
}

// ---------------- step-2 score: read k scratch ----------------
__global__ void __launch_bounds__(256) score2_kernel(
    const float* __restrict__ w_score, const float* __restrict__ q)
{
    const size_t row  = (size_t)blockIdx.x * 8 + (threadIdx.x >> 5);
    const int    lane = threadIdx.x & 31;
    const int    n    = (int)(row >> 11);           // row / LL

    const float4 kv = *(const float4*)(g_k + row * HH + 4 * lane);
    const float4 qv = *(const float4*)(q + (size_t)n * HH + 4 * lane);
    const float4 wv = *(const float4*)(w_score + 4 * lane);

    float s = wv.x * acc_tanh(qv.x + kv.x)
            + wv.y * acc_tanh(qv.y + kv.y)
            + wv.z * acc_tanh(qv.z + kv.z)
            + wv.w * acc_tanh(qv.w + kv.w);
    #pragma unroll
    for (int off = 16; off > 0; off >>= 1)
        s += __shfl_xor_sync(0xffffffffu, s, off);
    if (lane == 0) g_logits[row] = s;
}

// ---------------- softmax + argmax (+ gather next input) ----------------
__global__ void __launch_bounds__(256) softmax_kernel(
    const float* __restrict__ enc_in, float* __restrict__ out,
    int step, int do_gather)
{
    __shared__ float smax[256];
    __shared__ int   sidx[256];
    __shared__ float ssum[256];
    const int n   = blockIdx.x;
    const int tid = threadIdx.x;
    const float* lg = g_logits + (size_t)n * LL;

    float v[8];
    float vmax = -1e30f; int vidx = 0;
    #pragma unroll
    for (int i = 0; i < 8; i++){
        int l = tid + i * 256;
        v[i] = lg[l];
        if (v[i] > vmax){ vmax = v[i]; vidx = l; }
    }
    smax[tid] = vmax; sidx[tid] = vidx;
    __syncthreads();
    for (int s = 128; s > 0; s >>= 1){
        if (tid < s){
            float ov = smax[tid + s]; int oi = sidx[tid + s];
            if (ov > smax[tid] || (ov == smax[tid] && oi < sidx[tid])){
                smax[tid] = ov; sidx[tid] = oi;
            }
        }
        __syncthreads();
    }
    const float m   = smax[0];
    const int   idx = sidx[0];
    __syncthreads();

    float e[8];
    float loc = 0.0f;
    #pragma unroll
    for (int i = 0; i < 8; i++){ e[i] = expf(v[i] - m); loc += e[i]; }
    ssum[tid] = loc;
    __syncthreads();
    for (int s = 128; s > 0; s >>= 1){
        if (tid < s) ssum[tid] += ssum[tid + s];
        __syncthreads();
    }
    const float inv = 1.0f / ssum[0];

    float* orow = out + ((size_t)n * 2 + step) * LL;
    #pragma unroll
    for (int i = 0; i < 8; i++) orow[tid + i * 256] = e[i] * inv;

    if (do_gather && tid < HH)
        g_x[n * HH + tid] = enc_in[((size_t)n * LL + idx) * HH + tid];
}

// ---------------- launch ----------------
extern "C" void kernel_launch(void* const* d_in, const int* in_sizes, int n_in,
                              void* d_out, int out_size)
{
    const float* enc_in  = (const float*)d_in[0];
    const float* enc_out = (const float*)d_in[1];
    const float* state0  = (const float*)d_in[2];
    const float* W_ih    = (const float*)d_in[3];
    const float* W_hh    = (const float*)d_in[4];
    const float* b_ih    = (const float*)d_in[5];
    const float* b_hh    = (const float*)d_in[6];
    const float* Wq      = (const float*)d_in[7];
    const float* Wk      = (const float*)d_in[8];
    const float* w_score = (const float*)d_in[9];
    float* out = (float*)d_out;

    float *p_x, *p_state, *p_q;
    cudaGetSymbolAddress((void**)&p_x, g_x);
    cudaGetSymbolAddress((void**)&p_state, g_state);
    cudaGetSymbolAddress((void**)&p_q, g_q);

    const int KQ_SMEM = 128 * HH * (int)sizeof(float);   // 64 KB
    cudaFuncSetAttribute(kq_kernel,
                         cudaFuncAttributeMaxDynamicSharedMemorySize, KQ_SMEM);

    // prologue
    init_x_kernel<<<(NN * HH + 255) / 256, 256>>>();
    pair_wk_kernel<<<HH / 2, HH>>>(Wk);
    // step 1
    gru_kernel<<<NN / GR, HH>>>(p_x, state0, W_ih, W_hh, b_ih, b_hh, Wq);
    kq_kernel<<<dim3(LL / 128, NN), 256, KQ_SMEM>>>(enc_out, w_score, p_q);
    softmax_kernel<<<NN, 256>>>(enc_in, out, 0, 1);
    // step 2
    gru_kernel<<<NN / GR, HH>>>(p_x, p_state, W_ih, W_hh, b_ih, b_hh, Wq);
    score2_kernel<<<(int)(((size_t)NN * LL) / 8), 256>>>(w_score, p_q);
    softmax_kernel<<<NN, 256>>>(enc_in, out, 1, 0);
}

// round 14
// speedup vs baseline: 2.6489x; 2.6489x over previous
#include <cuda_runtime.h>
#include <cuda_bf16.h>
#include <cstdint>
#include <cstddef>
#include <math.h>

#define NN 1024
#define LL 2048
#define HH 128

// ---------------- scratch (device globals; no allocation) ----------------
static __device__ float g_k[(size_t)NN * LL * HH];   // 1 GiB
static __device__ float g_logits[(size_t)NN * LL];
static __device__ float g_x[NN * HH];
static __device__ float g_state[NN * HH];
static __device__ float g_q[NN * HH];
// Wk as pre-swizzled bf16 b-fragments:
// idx = (((plane*8 + kstep)*16 + ntg)*2 + breg)*32 + lane
// value = bf16x2 of B[o][k], B[o][k+1], o = ntg*8 + lane/4,
//         k = kstep*16 + 2*(lane%4) + breg*8; plane 0 = hi, 1 = lo
static __device__ uint32_t g_Wb[16384];

// ---------------- math helpers ----------------
__device__ __forceinline__ float ex2f(float x){ float r; asm("ex2.approx.f32 %0, %1;" : "=f"(r) : "f"(x)); return r; }
__device__ __forceinline__ float rcpaf(float x){ float r; asm("rcp.approx.f32 %0, %1;" : "=f"(r) : "f"(x)); return r; }

// tanh(x) = 1 - 2/(1+e^{2x}); ex2 + rcp + one Newton step  (~1e-7 abs err)
__device__ __forceinline__ float acc_tanh(float x){
    float y = fminf(x * 2.8853900817779268f, 80.0f);   // 2/ln(2)
    float e = ex2f(y);
    float d = e + 1.0f;
    float r = rcpaf(d);
    r = r * fmaf(-d, r, 2.0f);                         // Newton
    return fmaf(-2.0f, r, 1.0f);
}

__device__ __forceinline__ void mma_bf16(float* c,
    uint32_t a0, uint32_t a1, uint32_t a2, uint32_t a3,
    uint32_t b0, uint32_t b1)
{
    asm volatile(
        "mma.sync.aligned.m16n8k16.row.col.f32.bf16.bf16.f32 "
        "{%0,%1,%2,%3}, {%4,%5,%6,%7}, {%8,%9}, {%0,%1,%2,%3};"
        : "+f"(c[0]), "+f"(c[1]), "+f"(c[2]), "+f"(c[3])
        : "r"(a0), "r"(a1), "r"(a2), "r"(a3), "r"(b0), "r"(b1));
}

__device__ __forceinline__ uint32_t pack_bf16x2(__nv_bfloat16 lo, __nv_bfloat16 hi16){
    return (uint32_t)__bfloat16_as_ushort(lo) | ((uint32_t)__bfloat16_as_ushort(hi16) << 16);
}

// ---------------- init decoder input to ones ----------------
__global__ void init_x_kernel(){
    int i = blockIdx.x * blockDim.x + threadIdx.x;
    if (i < NN * HH) g_x[i] = 1.0f;
}

// ---------------- build swizzled bf16 B fragments (once per replay) ------
__global__ void __launch_bounds__(256) build_wb_kernel(const float* __restrict__ Wk){
    int e = blockIdx.x * 256 + threadIdx.x;       // 64 blocks -> 16384
    int lane  = e & 31;
    int breg  = (e >> 5) & 1;
    int ntg   = (e >> 6) & 15;
    int kstep = (e >> 10) & 7;
    int plane = (e >> 13) & 1;
    int o = ntg * 8 + (lane >> 2);
    int k = kstep * 16 + 2 * (lane & 3) + breg * 8;
    float x0 = Wk[o * HH + k];
    float x1 = Wk[o * HH + k + 1];
    __nv_bfloat16 h0 = __float2bfloat16(x0);
    __nv_bfloat16 h1 = __float2bfloat16(x1);
    __nv_bfloat16 v0, v1;
    if (plane == 0){ v0 = h0; v1 = h1; }
    else {
        v0 = __float2bfloat16(x0 - __bfloat162float(h0));
        v1 = __float2bfloat16(x1 - __bfloat162float(h1));
    }
    g_Wb[e] = pack_bf16x2(v0, v1);
}

// ---------------- GRU cell + q projection ----------------
#define GR 8
__global__ void __launch_bounds__(HH) gru_kernel(
    const float* __restrict__ x_in, const float* __restrict__ h_in,
    const float* __restrict__ W_ih, const float* __restrict__ W_hh,
    const float* __restrict__ b_ih, const float* __restrict__ b_hh,
    const float* __restrict__ Wq)
{
    __shared__ float x_s[GR][HH];
    __shared__ float h_s[GR][HH];
    __shared__ float hn_s[GR][HH];
    const int n0 = blockIdx.x * GR;
    const int j  = threadIdx.x;
    for (int r = 0; r < GR; r++){
        x_s[r][j] = x_in[(n0 + r) * HH + j];
        h_s[r][j] = h_in[(n0 + r) * HH + j];
    }
    __syncthreads();

    float ar[GR], az[GR], anx[GR], anh[GR];
    #pragma unroll
    for (int r = 0; r < GR; r++){ ar[r] = az[r] = anx[r] = anh[r] = 0.0f; }

    const float4* Wr = (const float4*)(W_ih + (size_t)j * HH);
    const float4* Wz = (const float4*)(W_ih + (size_t)(HH + j) * HH);
    const float4* Wn = (const float4*)(W_ih + (size_t)(2 * HH + j) * HH);
    const float4* Vr = (const float4*)(W_hh + (size_t)j * HH);
    const float4* Vz = (const float4*)(W_hh + (size_t)(HH + j) * HH);
    const float4* Vn = (const float4*)(W_hh + (size_t)(2 * HH + j) * HH);

    for (int h4 = 0; h4 < HH / 4; h4++){
        float4 wr = Wr[h4], wz = Wz[h4], wn = Wn[h4];
        float4 vr = Vr[h4], vz = Vz[h4], vn = Vn[h4];
        #pragma unroll
        for (int r = 0; r < GR; r++){
            float4 xx = *(const float4*)&x_s[r][h4 * 4];
            float4 hh = *(const float4*)&h_s[r][h4 * 4];
            ar[r]  += wr.x*xx.x + wr.y*xx.y + wr.z*xx.z + wr.w*xx.w
                    + vr.x*hh.x + vr.y*hh.y + vr.z*hh.z + vr.w*hh.w;
            az[r]  += wz.x*xx.x + wz.y*xx.y + wz.z*xx.z + wz.w*xx.w
                    + vz.x*hh.x + vz.y*hh.y + vz.z*hh.z + vz.w*hh.w;
            anx[r] += wn.x*xx.x + wn.y*xx.y + wn.z*xx.z + wn.w*xx.w;
            anh[r] += vn.x*hh.x + vn.y*hh.y + vn.z*hh.z + vn.w*hh.w;
        }
    }
    const float br  = b_ih[j] + b_hh[j];
    const float bz  = b_ih[HH + j] + b_hh[HH + j];
    const float bnx = b_ih[2 * HH + j];
    const float bnh = b_hh[2 * HH + j];
    #pragma unroll
    for (int r = 0; r < GR; r++){
        float rr = 1.0f / (1.0f + expf(-(ar[r] + br)));
        float zz = 1.0f / (1.0f + expf(-(az[r] + bz)));
        float nn = tanhf(anx[r] + bnx + rr * (anh[r] + bnh));
        float hp = (1.0f - zz) * nn + zz * h_s[r][j];
        hn_s[r][j] = hp;
        g_state[(n0 + r) * HH + j] = hp;
    }
    __syncthreads();
    float aq[GR];
    #pragma unroll
    for (int r = 0; r < GR; r++) aq[r] = 0.0f;
    const float4* Q = (const float4*)(Wq + (size_t)j * HH);
    for (int h4 = 0; h4 < HH / 4; h4++){
        float4 wq = Q[h4];
        #pragma unroll
        for (int r = 0; r < GR; r++){
            float4 hh = *(const float4*)&hn_s[r][h4 * 4];
            aq[r] += wq.x*hh.x + wq.y*hh.y + wq.z*hh.z + wq.w*hh.w;
        }
    }
    #pragma unroll
    for (int r = 0; r < GR; r++) g_q[(n0 + r) * HH + j] = aq[r];
}

// ---------------- fused k-GEMM (HMMA bf16 split) + step-1 score ----------
// grid (32, 1024): blockIdx.y = n, blockIdx.x = 64-row L-tile.
// 256 threads, 8 warps = 4 m-groups x 2 n-halves. Warp: m16 rows
// (rowbase = 16*mgroup) x 64 cols (nhalf*64), 8 n-tiles of n8.
// eo tile staged to smem as hi/lo bf16 planes (pitch 136 bf16 ->
// bank-shift 4/row, conflict-free frag LDS). Wk b-frags from g_Wb
// (coalesced LDG.b32, L1-hot). 3 combos hh + hl + lh into fp32 acc.
#define APITCH 136
#define SM_AHI 0
#define SM_ALO 17408
#define SM_QS  34816
#define SM_WS  35328
#define SM_PART 35840
#define KQ_SMEM 36352

__global__ void __launch_bounds__(256) kq_kernel(
    const float* __restrict__ eo,
    const float* __restrict__ w_score, const float* __restrict__ q)
{
    extern __shared__ char sm[];
    __nv_bfloat16* Ahi = (__nv_bfloat16*)(sm + SM_AHI);
    __nv_bfloat16* Alo = (__nv_bfloat16*)(sm + SM_ALO);
    float* qs   = (float*)(sm + SM_QS);
    float* ws   = (float*)(sm + SM_WS);
    float* part = (float*)(sm + SM_PART);      // [2][64]

    const int n    = blockIdx.y;
    const int l0   = blockIdx.x * 64;
    const int tid  = threadIdx.x;
    const int wid  = tid >> 5;
    const int lane = tid & 31;
    const int mg   = wid & 3;                  // m-group (16 rows)
    const int nh   = wid >> 2;                 // n-half (64 cols)
    const int g    = lane >> 2;                // quad row
    const int tig  = lane & 3;

    // stage eo tile (64x128 fp32) -> hi/lo bf16 planes
    {
        const float4* src = (const float4*)(eo + ((size_t)n * LL + l0) * HH);
        #pragma unroll
        for (int it = 0; it < 8; it++){
            int idx = tid + it * 256;          // 2048 float4
            int row = idx >> 5;
            int c4  = idx & 31;                // k = 4*c4
            float4 v = src[idx];
            __nv_bfloat16 h0 = __float2bfloat16(v.x);
            __nv_bfloat16 h1 = __float2bfloat16(v.y);
            __nv_bfloat16 h2 = __float2bfloat16(v.z);
            __nv_bfloat16 h3 = __float2bfloat16(v.w);
            __nv_bfloat16 e0 = __float2bfloat16(v.x - __bfloat162float(h0));
            __nv_bfloat16 e1 = __float2bfloat16(v.y - __bfloat162float(h1));
            __nv_bfloat16 e2 = __float2bfloat16(v.z - __bfloat162float(h2));
            __nv_bfloat16 e3 = __float2bfloat16(v.w - __bfloat162float(h3));
            uint2 hv = make_uint2(pack_bf16x2(h0, h1), pack_bf16x2(h2, h3));
            uint2 lv = make_uint2(pack_bf16x2(e0, e1), pack_bf16x2(e2, e3));
            *(uint2*)(Ahi + row * APITCH + c4 * 4) = hv;
            *(uint2*)(Alo + row * APITCH + c4 * 4) = lv;
        }
        if (tid < HH){
            qs[tid] = q[(size_t)n * HH + tid];
            ws[tid] = w_score[tid];
        }
    }
    __syncthreads();

    float acc[8][4];
    #pragma unroll
    for (int nt = 0; nt < 8; nt++)
        #pragma unroll
        for (int i = 0; i < 4; i++) acc[nt][i] = 0.0f;

    const int rowbase = mg * 16;
    const uint32_t* wb = g_Wb;

    #pragma unroll
    for (int kstep = 0; kstep < 8; kstep++){
        const int kk = kstep * 16 + 2 * tig;   // even
        const int offA = (rowbase + g) * APITCH + kk;
        uint32_t ah0 = *(const uint32_t*)(Ahi + offA);
        uint32_t ah1 = *(const uint32_t*)(Ahi + offA + 8 * APITCH);
        uint32_t ah2 = *(const uint32_t*)(Ahi + offA + 8);
        uint32_t ah3 = *(const uint32_t*)(Ahi + offA + 8 * APITCH + 8);
        uint32_t al0 = *(const uint32_t*)(Alo + offA);
        uint32_t al1 = *(const uint32_t*)(Alo + offA + 8 * APITCH);
        uint32_t al2 = *(const uint32_t*)(Alo + offA + 8);
        uint32_t al3 = *(const uint32_t*)(Alo + offA + 8 * APITCH + 8);
        #pragma unroll
        for (int nt = 0; nt < 8; nt++){
            const int ntg = nh * 8 + nt;
            const int base = kstep * 1024 + ntg * 64 + lane;
            uint32_t bh0 = wb[base];
            uint32_t bh1 = wb[base + 32];
            uint32_t bl0 = wb[8192 + base];
            uint32_t bl1 = wb[8192 + base + 32];
            mma_bf16(acc[nt], ah0, ah1, ah2, ah3, bh0, bh1);   // hh
            mma_bf16(acc[nt], ah0, ah1, ah2, ah3, bl0, bl1);   // hl
            mma_bf16(acc[nt], al0, al1, al2, al3, bh0, bh1);   // lh
        }
    }

    // epilogue: store k, fused logits
    const int r0 = rowbase + g;
    const int r1 = r0 + 8;
    float s0 = 0.0f, s1 = 0.0f;
    #pragma unroll
    for (int nt = 0; nt < 8; nt++){
        const int c0 = nh * 64 + nt * 8 + 2 * tig;
        float* k0p = g_k + ((size_t)n * LL + l0 + r0) * HH + c0;
        float* k1p = g_k + ((size_t)n * LL + l0 + r1) * HH + c0;
        *(float2*)k0p = make_float2(acc[nt][0], acc[nt][1]);
        *(float2*)k1p = make_float2(acc[nt][2], acc[nt][3]);
        const float w0 = ws[c0], w1 = ws[c0 + 1];
        const float q0 = qs[c0], q1 = qs[c0 + 1];
        s0 += w0 * acc_tanh(q0 + acc[nt][0]) + w1 * acc_tanh(q1 + acc[nt][1]);
        s1 += w0 * acc_tanh(q0 + acc[nt][2]) + w1 * acc_tanh(q1 + acc[nt][3]);
    }
    // reduce over tig (4 lanes share a row)
    #pragma unroll
    for (int off = 1; off < 4; off <<= 1){
        s0 += __shfl_xor_sync(0xffffffffu, s0, off);
        s1 += __shfl_xor_sync(0xffffffffu, s1, off);
    }
    if (tig == 0){
        part[nh * 64 + r0] = s0;
        part[nh * 64 + r1] = s1;
    }
    __syncthreads();
    if (tid < 64)
        g_logits[(size_t)n * LL + l0 + tid] = part[tid] + part[64 + tid];
}

// ---------------- step-2 score: read k scratch ----------------
__global__ void __launch_bounds__(256) score2_kernel(
    const float* __restrict__ w_score, const float* __restrict__ q)
{
    const size_t row  = (size_t)blockIdx.x * 8 + (threadIdx.x >> 5);
    const int    lane = threadIdx.x & 31;
    const int    n    = (int)(row >> 11);           // row / LL

    const float4 kv = *(const float4*)(g_k + row * HH + 4 * lane);
    const float4 qv = *(const float4*)(q + (size_t)n * HH + 4 * lane);
    const float4 wv = *(const float4*)(w_score + 4 * lane);

    float s = wv.x * acc_tanh(qv.x + kv.x)
            + wv.y * acc_tanh(qv.y + kv.y)
            + wv.z * acc_tanh(qv.z + kv.z)
            + wv.w * acc_tanh(qv.w + kv.w);
    #pragma unroll
    for (int off = 16; off > 0; off >>= 1)
        s += __shfl_xor_sync(0xffffffffu, s, off);
    if (lane == 0) g_logits[row] = s;
}

// ---------------- softmax + argmax (+ gather next input) ----------------
__global__ void __launch_bounds__(256) softmax_kernel(
    const float* __restrict__ enc_in, float* __restrict__ out,
    int step, int do_gather)
{
    __shared__ float smax[256];
    __shared__ int   sidx[256];
    __shared__ float ssum[256];
    const int n   = blockIdx.x;
    const int tid = threadIdx.x;
    const float* lg = g_logits + (size_t)n * LL;

    float v[8];
    float vmax = -1e30f; int vidx = 0;
    #pragma unroll
    for (int i = 0; i < 8; i++){
        int l = tid + i * 256;
        v[i] = lg[l];
        if (v[i] > vmax){ vmax = v[i]; vidx = l; }
    }
    smax[tid] = vmax; sidx[tid] = vidx;
    __syncthreads();
    for (int s = 128; s > 0; s >>= 1){
        if (tid < s){
            float ov = smax[tid + s]; int oi = sidx[tid + s];
            if (ov > smax[tid] || (ov == smax[tid] && oi < sidx[tid])){
                smax[tid] = ov; sidx[tid] = oi;
            }
        }
        __syncthreads();
    }
    const float m   = smax[0];
    const int   idx = sidx[0];
    __syncthreads();

    float e[8];
    float loc = 0.0f;
    #pragma unroll
    for (int i = 0; i < 8; i++){ e[i] = expf(v[i] - m); loc += e[i]; }
    ssum[tid] = loc;
    __syncthreads();
    for (int s = 128; s > 0; s >>= 1){
        if (tid < s) ssum[tid] += ssum[tid + s];
        __syncthreads();
    }
    const float inv = 1.0f / ssum[0];

    float* orow = out + ((size_t)n * 2 + step) * LL;
    #pragma unroll
    for (int i = 0; i < 8; i++) orow[tid + i * 256] = e[i] * inv;

    if (do_gather && tid < HH)
        g_x[n * HH + tid] = enc_in[((size_t)n * LL + idx) * HH + tid];
}

// ---------------- launch ----------------
extern "C" void kernel_launch(void* const* d_in, const int* in_sizes, int n_in,
                              void* d_out, int out_size)
{
    const float* enc_in  = (const float*)d_in[0];
    const float* enc_out = (const float*)d_in[1];
    const float* state0  = (const float*)d_in[2];
    const float* W_ih    = (const float*)d_in[3];
    const float* W_hh    = (const float*)d_in[4];
    const float* b_ih    = (const float*)d_in[5];
    const float* b_hh    = (const float*)d_in[6];
    const float* Wq      = (const float*)d_in[7];
    const float* Wk      = (const float*)d_in[8];
    const float* w_score = (const float*)d_in[9];
    float* out = (float*)d_out;

    float *p_x, *p_state, *p_q;
    cudaGetSymbolAddress((void**)&p_x, g_x);
    cudaGetSymbolAddress((void**)&p_state, g_state);
    cudaGetSymbolAddress((void**)&p_q, g_q);

    cudaFuncSetAttribute(kq_kernel,
                         cudaFuncAttributeMaxDynamicSharedMemorySize, KQ_SMEM);

    // prologue
    init_x_kernel<<<(NN * HH + 255) / 256, 256>>>();
    build_wb_kernel<<<64, 256>>>(Wk);
    // step 1
    gru_kernel<<<NN / GR, HH>>>(p_x, state0, W_ih, W_hh, b_ih, b_hh, Wq);
    kq_kernel<<<dim3(LL / 64, NN), 256, KQ_SMEM>>>(enc_out, w_score, p_q);
    softmax_kernel<<<NN, 256>>>(enc_in, out, 0, 1);
    // step 2
    gru_kernel<<<NN / GR, HH>>>(p_x, p_state, W_ih, W_hh, b_ih, b_hh, Wq);
    score2_kernel<<<(int)(((size_t)NN * LL) / 8), 256>>>(w_score, p_q);
    softmax_kernel<<<NN, 256>>>(enc_in, out, 1, 0);
}

// round 15
// speedup vs baseline: 3.1538x; 1.1906x over previous
#include <cuda_runtime.h>
#include <cuda_bf16.h>
#include <cstdint>
#include <cstddef>
#include <math.h>

#define NN 1024
#define LL 2048
#define HH 128

// ---------------- scratch (device globals; no allocation) ----------------
static __device__ float g_k[(size_t)NN * LL * HH];   // 1 GiB
static __device__ float g_logits[(size_t)NN * LL];
static __device__ float g_x[NN * HH];
static __device__ float g_state[NN * HH];
static __device__ float g_q[NN * HH];
// Wk as pre-swizzled bf16 b-fragments, uint4-packed (2 n-tiles per entry):
// idx4 = ((plane*8 + kstep)*8 + ntpair)*32 + lane
// .x = bf16x2 B[o0][k0],B[o0][k0+1]   (b0 of nt=2*ntpair)
// .y = bf16x2 B[o0][k1],B[o0][k1+1]   (b1 of nt=2*ntpair)
// .z/.w same for nt=2*ntpair+1
// o(nt) = nt*8 + lane/4, k0 = kstep*16 + 2*(lane%4), k1 = k0 + 8
// plane 0 = hi bf16, plane 1 = lo residual
static __device__ uint4 g_Wb4[4096];

// ---------------- math helpers ----------------
__device__ __forceinline__ float ex2f(float x){ float r; asm("ex2.approx.f32 %0, %1;" : "=f"(r) : "f"(x)); return r; }
__device__ __forceinline__ float rcpaf(float x){ float r; asm("rcp.approx.f32 %0, %1;" : "=f"(r) : "f"(x)); return r; }

// tanh(x) = 1 - 2/(1+e^{2x}); ex2 + rcp + one Newton step  (~1e-7 abs err)
__device__ __forceinline__ float acc_tanh(float x){
    float y = fminf(x * 2.8853900817779268f, 80.0f);   // 2/ln(2)
    float e = ex2f(y);
    float d = e + 1.0f;
    float r = rcpaf(d);
    r = r * fmaf(-d, r, 2.0f);                         // Newton
    return fmaf(-2.0f, r, 1.0f);
}

__device__ __forceinline__ void mma_bf16(float* c,
    uint32_t a0, uint32_t a1, uint32_t a2, uint32_t a3,
    uint32_t b0, uint32_t b1)
{
    asm volatile(
        "mma.sync.aligned.m16n8k16.row.col.f32.bf16.bf16.f32 "
        "{%0,%1,%2,%3}, {%4,%5,%6,%7}, {%8,%9}, {%0,%1,%2,%3};"
        : "+f"(c[0]), "+f"(c[1]), "+f"(c[2]), "+f"(c[3])
        : "r"(a0), "r"(a1), "r"(a2), "r"(a3), "r"(b0), "r"(b1));
}

__device__ __forceinline__ void ldsm_x4(uint32_t& r0, uint32_t& r1,
                                        uint32_t& r2, uint32_t& r3, uint32_t addr)
{
    asm volatile("ldmatrix.sync.aligned.m8n8.x4.shared.b16 {%0,%1,%2,%3}, [%4];"
        : "=r"(r0), "=r"(r1), "=r"(r2), "=r"(r3) : "r"(addr));
}

__device__ __forceinline__ uint32_t pack_bf16x2(__nv_bfloat16 lo, __nv_bfloat16 hi16){
    return (uint32_t)__bfloat16_as_ushort(lo) | ((uint32_t)__bfloat16_as_ushort(hi16) << 16);
}

// ---------------- init decoder input to ones ----------------
__global__ void init_x_kernel(){
    int i = blockIdx.x * blockDim.x + threadIdx.x;
    if (i < NN * HH) g_x[i] = 1.0f;
}

// ---------------- build swizzled bf16 B fragments (once per replay) ------
__global__ void __launch_bounds__(256) build_wb_kernel(const float* __restrict__ Wk){
    int e = blockIdx.x * 256 + threadIdx.x;       // 16 blocks -> 4096
    int lane  = e & 31;
    int pp    = (e >> 5) & 7;                     // ntpair
    int kstep = (e >> 8) & 7;
    int plane = (e >> 11) & 1;
    int o0 = (2 * pp) * 8 + (lane >> 2);
    int o1 = o0 + 8;
    int k0 = kstep * 16 + 2 * (lane & 3);
    int k1 = k0 + 8;

    auto cv = [&](int o, int k) -> __nv_bfloat16 {
        float x = Wk[o * HH + k];
        __nv_bfloat16 h = __float2bfloat16(x);
        if (plane == 0) return h;
        return __float2bfloat16(x - __bfloat162float(h));
    };
    uint4 v;
    v.x = pack_bf16x2(cv(o0, k0), cv(o0, k0 + 1));
    v.y = pack_bf16x2(cv(o0, k1), cv(o0, k1 + 1));
    v.z = pack_bf16x2(cv(o1, k0), cv(o1, k0 + 1));
    v.w = pack_bf16x2(cv(o1, k1), cv(o1, k1 + 1));
    g_Wb4[e] = v;
}

// ---------------- GRU cell + q projection ----------------
#define GR 8
__global__ void __launch_bounds__(HH) gru_kernel(
    const float* __restrict__ x_in, const float* __restrict__ h_in,
    const float* __restrict__ W_ih, const float* __restrict__ W_hh,
    const float* __restrict__ b_ih, const float* __restrict__ b_hh,
    const float* __restrict__ Wq)
{
    __shared__ float x_s[GR][HH];
    __shared__ float h_s[GR][HH];
    __shared__ float hn_s[GR][HH];
    const int n0 = blockIdx.x * GR;
    const int j  = threadIdx.x;
    for (int r = 0; r < GR; r++){
        x_s[r][j] = x_in[(n0 + r) * HH + j];
        h_s[r][j] = h_in[(n0 + r) * HH + j];
    }
    __syncthreads();

    float ar[GR], az[GR], anx[GR], anh[GR];
    #pragma unroll
    for (int r = 0; r < GR; r++){ ar[r] = az[r] = anx[r] = anh[r] = 0.0f; }

    const float4* Wr = (const float4*)(W_ih + (size_t)j * HH);
    const float4* Wz = (const float4*)(W_ih + (size_t)(HH + j) * HH);
    const float4* Wn = (const float4*)(W_ih + (size_t)(2 * HH + j) * HH);
    const float4* Vr = (const float4*)(W_hh + (size_t)j * HH);
    const float4* Vz = (const float4*)(W_hh + (size_t)(HH + j) * HH);
    const float4* Vn = (const float4*)(W_hh + (size_t)(2 * HH + j) * HH);

    for (int h4 = 0; h4 < HH / 4; h4++){
        float4 wr = Wr[h4], wz = Wz[h4], wn = Wn[h4];
        float4 vr = Vr[h4], vz = Vz[h4], vn = Vn[h4];
        #pragma unroll
        for (int r = 0; r < GR; r++){
            float4 xx = *(const float4*)&x_s[r][h4 * 4];
            float4 hh = *(const float4*)&h_s[r][h4 * 4];
            ar[r]  += wr.x*xx.x + wr.y*xx.y + wr.z*xx.z + wr.w*xx.w
                    + vr.x*hh.x + vr.y*hh.y + vr.z*hh.z + vr.w*hh.w;
            az[r]  += wz.x*xx.x + wz.y*xx.y + wz.z*xx.z + wz.w*xx.w
                    + vz.x*hh.x + vz.y*hh.y + vz.z*hh.z + vz.w*hh.w;
            anx[r] += wn.x*xx.x + wn.y*xx.y + wn.z*xx.z + wn.w*xx.w;
            anh[r] += vn.x*hh.x + vn.y*hh.y + vn.z*hh.z + vn.w*hh.w;
        }
    }
    const float br  = b_ih[j] + b_hh[j];
    const float bz  = b_ih[HH + j] + b_hh[HH + j];
    const float bnx = b_ih[2 * HH + j];
    const float bnh = b_hh[2 * HH + j];
    #pragma unroll
    for (int r = 0; r < GR; r++){
        float rr = 1.0f / (1.0f + expf(-(ar[r] + br)));
        float zz = 1.0f / (1.0f + expf(-(az[r] + bz)));
        float nn = tanhf(anx[r] + bnx + rr * (anh[r] + bnh));
        float hp = (1.0f - zz) * nn + zz * h_s[r][j];
        hn_s[r][j] = hp;
        g_state[(n0 + r) * HH + j] = hp;
    }
    __syncthreads();
    float aq[GR];
    #pragma unroll
    for (int r = 0; r < GR; r++) aq[r] = 0.0f;
    const float4* Q = (const float4*)(Wq + (size_t)j * HH);
    for (int h4 = 0; h4 < HH / 4; h4++){
        float4 wq = Q[h4];
        #pragma unroll
        for (int r = 0; r < GR; r++){
            float4 hh = *(const float4*)&hn_s[r][h4 * 4];
            aq[r] += wq.x*hh.x + wq.y*hh.y + wq.z*hh.z + wq.w*hh.w;
        }
    }
    #pragma unroll
    for (int r = 0; r < GR; r++) g_q[(n0 + r) * HH + j] = aq[r];
}

// ---------------- fused k-GEMM (HMMA bf16 split) + step-1 score ----------
// grid (32, 1024): blockIdx.y = n, blockIdx.x = 64-row L-tile.
// 256 threads, 8 warps = 4 m-groups x 2 n-halves. Warp: m16 rows x 64 cols.
// A via ldmatrix.x4 from smem hi/lo planes (pitch 136 bf16, conflict-free);
// B via LDG.128 uint4 fragments (L1-hot 64 KB). 3 combos hh + hl + lh.
#define APITCH 136
#define SM_AHI 0
#define SM_ALO 17408
#define SM_QS  34816
#define SM_WS  35328
#define SM_PART 35840
#define KQ_SMEM 36352

__global__ void __launch_bounds__(256) kq_kernel(
    const float* __restrict__ eo,
    const float* __restrict__ w_score, const float* __restrict__ q)
{
    extern __shared__ char sm[];
    __nv_bfloat16* Ahi = (__nv_bfloat16*)(sm + SM_AHI);
    __nv_bfloat16* Alo = (__nv_bfloat16*)(sm + SM_ALO);
    float* qs   = (float*)(sm + SM_QS);
    float* ws   = (float*)(sm + SM_WS);
    float* part = (float*)(sm + SM_PART);      // [2][64]

    const int n    = blockIdx.y;
    const int l0   = blockIdx.x * 64;
    const int tid  = threadIdx.x;
    const int wid  = tid >> 5;
    const int lane = tid & 31;
    const int mg   = wid & 3;                  // m-group (16 rows)
    const int nh   = wid >> 2;                 // n-half (64 cols)
    const int g    = lane >> 2;                // quad row
    const int tig  = lane & 3;

    // stage eo tile (64x128 fp32) -> hi/lo bf16 planes
    {
        const float4* src = (const float4*)(eo + ((size_t)n * LL + l0) * HH);
        #pragma unroll
        for (int it = 0; it < 8; it++){
            int idx = tid + it * 256;          // 2048 float4
            int row = idx >> 5;
            int c4  = idx & 31;                // k = 4*c4
            float4 v = src[idx];
            __nv_bfloat16 h0 = __float2bfloat16(v.x);
            __nv_bfloat16 h1 = __float2bfloat16(v.y);
            __nv_bfloat16 h2 = __float2bfloat16(v.z);
            __nv_bfloat16 h3 = __float2bfloat16(v.w);
            __nv_bfloat16 e0 = __float2bfloat16(v.x - __bfloat162float(h0));
            __nv_bfloat16 e1 = __float2bfloat16(v.y - __bfloat162float(h1));
            __nv_bfloat16 e2 = __float2bfloat16(v.z - __bfloat162float(h2));
            __nv_bfloat16 e3 = __float2bfloat16(v.w - __bfloat162float(h3));
            uint2 hv = make_uint2(pack_bf16x2(h0, h1), pack_bf16x2(h2, h3));
            uint2 lv = make_uint2(pack_bf16x2(e0, e1), pack_bf16x2(e2, e3));
            *(uint2*)(Ahi + row * APITCH + c4 * 4) = hv;
            *(uint2*)(Alo + row * APITCH + c4 * 4) = lv;
        }
        if (tid < HH){
            qs[tid] = q[(size_t)n * HH + tid];
            ws[tid] = w_score[tid];
        }
    }
    __syncthreads();

    float acc[8][4];
    #pragma unroll
    for (int nt = 0; nt < 8; nt++)
        #pragma unroll
        for (int i = 0; i < 4; i++) acc[nt][i] = 0.0f;

    const int rowbase = mg * 16;
    // ldmatrix x4 lane->address map: lanes 0-7 m0(r, kk), 8-15 m1(r+8, kk),
    // 16-23 m2(r, kk+8), 24-31 m3(r+8, kk+8)
    const int lq   = lane >> 3;
    const int lrow = rowbase + (lane & 7) + (lq & 1) * 8;
    const int lcol = (lq >> 1) * 8;
    const uint32_t ahi_b = (uint32_t)__cvta_generic_to_shared(Ahi)
                         + (uint32_t)(lrow * APITCH + lcol) * 2u;
    const uint32_t alo_b = (uint32_t)__cvta_generic_to_shared(Alo)
                         + (uint32_t)(lrow * APITCH + lcol) * 2u;
    const uint4* wb4 = g_Wb4;

    #pragma unroll
    for (int kstep = 0; kstep < 8; kstep++){
        uint32_t ah0, ah1, ah2, ah3, al0, al1, al2, al3;
        ldsm_x4(ah0, ah1, ah2, ah3, ahi_b + kstep * 32u);   // 16 bf16 = 32 B
        ldsm_x4(al0, al1, al2, al3, alo_b + kstep * 32u);
        #pragma unroll
        for (int p = 0; p < 4; p++){
            const int pp = nh * 4 + p;                       // global ntpair
            uint4 Bh = wb4[(0 * 8 + kstep) * 256 + pp * 32 + lane];
            uint4 Bl = wb4[(1 * 8 + kstep) * 256 + pp * 32 + lane];
            mma_bf16(acc[2 * p],     ah0, ah1, ah2, ah3, Bh.x, Bh.y);  // hh
            mma_bf16(acc[2 * p],     ah0, ah1, ah2, ah3, Bl.x, Bl.y);  // hl
            mma_bf16(acc[2 * p],     al0, al1, al2, al3, Bh.x, Bh.y);  // lh
            mma_bf16(acc[2 * p + 1], ah0, ah1, ah2, ah3, Bh.z, Bh.w);
            mma_bf16(acc[2 * p + 1], ah0, ah1, ah2, ah3, Bl.z, Bl.w);
            mma_bf16(acc[2 * p + 1], al0, al1, al2, al3, Bh.z, Bh.w);
        }
    }

    // epilogue: store k, fused logits
    const int r0 = rowbase + g;
    const int r1 = r0 + 8;
    float s0 = 0.0f, s1 = 0.0f;
    #pragma unroll
    for (int nt = 0; nt < 8; nt++){
        const int c0 = nh * 64 + nt * 8 + 2 * tig;
        float* k0p = g_k + ((size_t)n * LL + l0 + r0) * HH + c0;
        float* k1p = g_k + ((size_t)n * LL + l0 + r1) * HH + c0;
        *(float2*)k0p = make_float2(acc[nt][0], acc[nt][1]);
        *(float2*)k1p = make_float2(acc[nt][2], acc[nt][3]);
        const float w0 = ws[c0], w1 = ws[c0 + 1];
        const float q0 = qs[c0], q1 = qs[c0 + 1];
        s0 += w0 * acc_tanh(q0 + acc[nt][0]) + w1 * acc_tanh(q1 + acc[nt][1]);
        s1 += w0 * acc_tanh(q0 + acc[nt][2]) + w1 * acc_tanh(q1 + acc[nt][3]);
    }
    // reduce over tig (4 lanes share a row)
    #pragma unroll
    for (int off = 1; off < 4; off <<= 1){
        s0 += __shfl_xor_sync(0xffffffffu, s0, off);
        s1 += __shfl_xor_sync(0xffffffffu, s1, off);
    }
    if (tig == 0){
        part[nh * 64 + r0] = s0;
        part[nh * 64 + r1] = s1;
    }
    __syncthreads();
    if (tid < 64)
        g_logits[(size_t)n * LL + l0 + tid] = part[tid] + part[64 + tid];
}

// ---------------- step-2 score: read k scratch (4 rows per warp) ---------
__global__ void __launch_bounds__(256) score2_kernel(
    const float* __restrict__ w_score, const float* __restrict__ q)
{
    const size_t row0 = (size_t)blockIdx.x * 32 + (threadIdx.x >> 5) * 4;
    const int    lane = threadIdx.x & 31;

    const float4 wv = *(const float4*)(w_score + 4 * lane);
    float4 kv[4];
    #pragma unroll
    for (int r = 0; r < 4; r++)
        kv[r] = *(const float4*)(g_k + (row0 + r) * HH + 4 * lane);

    #pragma unroll
    for (int r = 0; r < 4; r++){
        const int n = (int)((row0 + r) >> 11);
        const float4 qv = *(const float4*)(q + (size_t)n * HH + 4 * lane);
        float s = wv.x * acc_tanh(qv.x + kv[r].x)
                + wv.y * acc_tanh(qv.y + kv[r].y)
                + wv.z * acc_tanh(qv.z + kv[r].z)
                + wv.w * acc_tanh(qv.w + kv[r].w);
        #pragma unroll
        for (int off = 16; off > 0; off >>= 1)
            s += __shfl_xor_sync(0xffffffffu, s, off);
        if (lane == 0) g_logits[row0 + r] = s;
    }
}

// ---------------- softmax + argmax (+ gather next input) ----------------
__global__ void __launch_bounds__(256) softmax_kernel(
    const float* __restrict__ enc_in, float* __restrict__ out,
    int step, int do_gather)
{
    __shared__ float smax[256];
    __shared__ int   sidx[256];
    __shared__ float ssum[256];
    const int n   = blockIdx.x;
    const int tid = threadIdx.x;
    const float* lg = g_logits + (size_t)n * LL;

    float v[8];
    float vmax = -1e30f; int vidx = 0;
    #pragma unroll
    for (int i = 0; i < 8; i++){
        int l = tid + i * 256;
        v[i] = lg[l];
        if (v[i] > vmax){ vmax = v[i]; vidx = l; }
    }
    smax[tid] = vmax; sidx[tid] = vidx;
    __syncthreads();
    for (int s = 128; s > 0; s >>= 1){
        if (tid < s){
            float ov = smax[tid + s]; int oi = sidx[tid + s];
            if (ov > smax[tid] || (ov == smax[tid] && oi < sidx[tid])){
                smax[tid] = ov; sidx[tid] = oi;
            }
        }
        __syncthreads();
    }
    const float m   = smax[0];
    const int   idx = sidx[0];
    __syncthreads();

    float e[8];
    float loc = 0.0f;
    #pragma unroll
    for (int i = 0; i < 8; i++){ e[i] = expf(v[i] - m); loc += e[i]; }
    ssum[tid] = loc;
    __syncthreads();
    for (int s = 128; s > 0; s >>= 1){
        if (tid < s) ssum[tid] += ssum[tid + s];
        __syncthreads();
    }
    const float inv = 1.0f / ssum[0];

    float* orow = out + ((size_t)n * 2 + step) * LL;
    #pragma unroll
    for (int i = 0; i < 8; i++) orow[tid + i * 256] = e[i] * inv;

    if (do_gather && tid < HH)
        g_x[n * HH + tid] = enc_in[((size_t)n * LL + idx) * HH + tid];
}

// ---------------- launch ----------------
extern "C" void kernel_launch(void* const* d_in, const int* in_sizes, int n_in,
                              void* d_out, int out_size)
{
    const float* enc_in  = (const float*)d_in[0];
    const float* enc_out = (const float*)d_in[1];
    const float* state0  = (const float*)d_in[2];
    const float* W_ih    = (const float*)d_in[3];
    const float* W_hh    = (const float*)d_in[4];
    const float* b_ih    = (const float*)d_in[5];
    const float* b_hh    = (const float*)d_in[6];
    const float* Wq      = (const float*)d_in[7];
    const float* Wk      = (const float*)d_in[8];
    const float* w_score = (const float*)d_in[9];
    float* out = (float*)d_out;

    float *p_x, *p_state, *p_q;
    cudaGetSymbolAddress((void**)&p_x, g_x);
    cudaGetSymbolAddress((void**)&p_state, g_state);
    cudaGetSymbolAddress((void**)&p_q, g_q);

    cudaFuncSetAttribute(kq_kernel,
                         cudaFuncAttributeMaxDynamicSharedMemorySize, KQ_SMEM);

    // prologue
    init_x_kernel<<<(NN * HH + 255) / 256, 256>>>();
    build_wb_kernel<<<16, 256>>>(Wk);
    // step 1
    gru_kernel<<<NN / GR, HH>>>(p_x, state0, W_ih, W_hh, b_ih, b_hh, Wq);
    kq_kernel<<<dim3(LL / 64, NN), 256, KQ_SMEM>>>(enc_out, w_score, p_q);
    softmax_kernel<<<NN, 256>>>(enc_in, out, 0, 1);
    // step 2
    gru_kernel<<<NN / GR, HH>>>(p_x, p_state, W_ih, W_hh, b_ih, b_hh, Wq);
    score2_kernel<<<(int)(((size_t)NN * LL) / 32), 256>>>(w_score, p_q);
    softmax_kernel<<<NN, 256>>>(enc_in, out, 1, 0);
}

// round 16
// speedup vs baseline: 3.2329x; 1.0251x over previous
#include <cuda_runtime.h>
#include <cuda_bf16.h>
#include <cstdint>
#include <cstddef>
#include <math.h>

#define NN 1024
#define LL 2048
#define HH 128

// ---------------- scratch (device globals; no allocation) ----------------
static __device__ float g_k[(size_t)NN * LL * HH];   // 1 GiB
static __device__ float g_logits[(size_t)NN * LL];
static __device__ float g_x[NN * HH];
static __device__ float g_state[NN * HH];
static __device__ float g_q[NN * HH];
// Wk as pre-swizzled bf16 b-fragments, uint4-packed (2 n-tiles per entry):
// idx4 = ((plane*8 + kstep)*8 + ntpair)*32 + lane
// o(nt) = nt*8 + lane/4, k0 = kstep*16 + 2*(lane%4), k1 = k0 + 8
// plane 0 = hi bf16, plane 1 = lo residual
static __device__ uint4 g_Wb4[4096];

// ---------------- math helpers ----------------
__device__ __forceinline__ float ex2f(float x){ float r; asm("ex2.approx.f32 %0, %1;" : "=f"(r) : "f"(x)); return r; }
__device__ __forceinline__ float rcpaf(float x){ float r; asm("rcp.approx.f32 %0, %1;" : "=f"(r) : "f"(x)); return r; }

// tanh(x) = 1 - 2/(1+e^{2x}); ex2 + rcp + one Newton step  (~1e-7 abs err)
__device__ __forceinline__ float acc_tanh(float x){
    float y = fminf(x * 2.8853900817779268f, 80.0f);   // 2/ln(2)
    float e = ex2f(y);
    float d = e + 1.0f;
    float r = rcpaf(d);
    r = r * fmaf(-d, r, 2.0f);                         // Newton
    return fmaf(-2.0f, r, 1.0f);
}

__device__ __forceinline__ void mma_bf16(float* c,
    uint32_t a0, uint32_t a1, uint32_t a2, uint32_t a3,
    uint32_t b0, uint32_t b1)
{
    asm volatile(
        "mma.sync.aligned.m16n8k16.row.col.f32.bf16.bf16.f32 "
        "{%0,%1,%2,%3}, {%4,%5,%6,%7}, {%8,%9}, {%0,%1,%2,%3};"
        : "+f"(c[0]), "+f"(c[1]), "+f"(c[2]), "+f"(c[3])
        : "r"(a0), "r"(a1), "r"(a2), "r"(a3), "r"(b0), "r"(b1));
}

__device__ __forceinline__ void ldsm_x4(uint32_t& r0, uint32_t& r1,
                                        uint32_t& r2, uint32_t& r3, uint32_t addr)
{
    asm volatile("ldmatrix.sync.aligned.m8n8.x4.shared.b16 {%0,%1,%2,%3}, [%4];"
        : "=r"(r0), "=r"(r1), "=r"(r2), "=r"(r3) : "r"(addr));
}

__device__ __forceinline__ uint32_t pack_bf16x2(__nv_bfloat16 lo, __nv_bfloat16 hi16){
    return (uint32_t)__bfloat16_as_ushort(lo) | ((uint32_t)__bfloat16_as_ushort(hi16) << 16);
}

// ---------------- init decoder input to ones ----------------
__global__ void init_x_kernel(){
    int i = blockIdx.x * blockDim.x + threadIdx.x;
    if (i < NN * HH) g_x[i] = 1.0f;
}

// ---------------- build swizzled bf16 B fragments (once per replay) ------
__global__ void __launch_bounds__(256) build_wb_kernel(const float* __restrict__ Wk){
    int e = blockIdx.x * 256 + threadIdx.x;       // 16 blocks -> 4096
    int lane  = e & 31;
    int pp    = (e >> 5) & 7;                     // ntpair
    int kstep = (e >> 8) & 7;
    int plane = (e >> 11) & 1;
    int o0 = (2 * pp) * 8 + (lane >> 2);
    int o1 = o0 + 8;
    int k0 = kstep * 16 + 2 * (lane & 3);
    int k1 = k0 + 8;

    auto cv = [&](int o, int k) -> __nv_bfloat16 {
        float x = Wk[o * HH + k];
        __nv_bfloat16 h = __float2bfloat16(x);
        if (plane == 0) return h;
        return __float2bfloat16(x - __bfloat162float(h));
    };
    uint4 v;
    v.x = pack_bf16x2(cv(o0, k0), cv(o0, k0 + 1));
    v.y = pack_bf16x2(cv(o0, k1), cv(o0, k1 + 1));
    v.z = pack_bf16x2(cv(o1, k0), cv(o1, k0 + 1));
    v.w = pack_bf16x2(cv(o1, k1), cv(o1, k1 + 1));
    g_Wb4[e] = v;
}

// ---------------- GRU cell + q projection ----------------
#define GR 8
__global__ void __launch_bounds__(HH) gru_kernel(
    const float* __restrict__ x_in, const float* __restrict__ h_in,
    const float* __restrict__ W_ih, const float* __restrict__ W_hh,
    const float* __restrict__ b_ih, const float* __restrict__ b_hh,
    const float* __restrict__ Wq)
{
    __shared__ float x_s[GR][HH];
    __shared__ float h_s[GR][HH];
    __shared__ float hn_s[GR][HH];
    const int n0 = blockIdx.x * GR;
    const int j  = threadIdx.x;
    for (int r = 0; r < GR; r++){
        x_s[r][j] = x_in[(n0 + r) * HH + j];
        h_s[r][j] = h_in[(n0 + r) * HH + j];
    }
    __syncthreads();

    float ar[GR], az[GR], anx[GR], anh[GR];
    #pragma unroll
    for (int r = 0; r < GR; r++){ ar[r] = az[r] = anx[r] = anh[r] = 0.0f; }

    const float4* Wr = (const float4*)(W_ih + (size_t)j * HH);
    const float4* Wz = (const float4*)(W_ih + (size_t)(HH + j) * HH);
    const float4* Wn = (const float4*)(W_ih + (size_t)(2 * HH + j) * HH);
    const float4* Vr = (const float4*)(W_hh + (size_t)j * HH);
    const float4* Vz = (const float4*)(W_hh + (size_t)(HH + j) * HH);
    const float4* Vn = (const float4*)(W_hh + (size_t)(2 * HH + j) * HH);

    for (int h4 = 0; h4 < HH / 4; h4++){
        float4 wr = Wr[h4], wz = Wz[h4], wn = Wn[h4];
        float4 vr = Vr[h4], vz = Vz[h4], vn = Vn[h4];
        #pragma unroll
        for (int r = 0; r < GR; r++){
            float4 xx = *(const float4*)&x_s[r][h4 * 4];
            float4 hh = *(const float4*)&h_s[r][h4 * 4];
            ar[r]  += wr.x*xx.x + wr.y*xx.y + wr.z*xx.z + wr.w*xx.w
                    + vr.x*hh.x + vr.y*hh.y + vr.z*hh.z + vr.w*hh.w;
            az[r]  += wz.x*xx.x + wz.y*xx.y + wz.z*xx.z + wz.w*xx.w
                    + vz.x*hh.x + vz.y*hh.y + vz.z*hh.z + vz.w*hh.w;
            anx[r] += wn.x*xx.x + wn.y*xx.y + wn.z*xx.z + wn.w*xx.w;
            anh[r] += vn.x*hh.x + vn.y*hh.y + vn.z*hh.z + vn.w*hh.w;
        }
    }
    const float br  = b_ih[j] + b_hh[j];
    const float bz  = b_ih[HH + j] + b_hh[HH + j];
    const float bnx = b_ih[2 * HH + j];
    const float bnh = b_hh[2 * HH + j];
    #pragma unroll
    for (int r = 0; r < GR; r++){
        float rr = 1.0f / (1.0f + expf(-(ar[r] + br)));
        float zz = 1.0f / (1.0f + expf(-(az[r] + bz)));
        float nn = tanhf(anx[r] + bnx + rr * (anh[r] + bnh));
        float hp = (1.0f - zz) * nn + zz * h_s[r][j];
        hn_s[r][j] = hp;
        g_state[(n0 + r) * HH + j] = hp;
    }
    __syncthreads();
    float aq[GR];
    #pragma unroll
    for (int r = 0; r < GR; r++) aq[r] = 0.0f;
    const float4* Q = (const float4*)(Wq + (size_t)j * HH);
    for (int h4 = 0; h4 < HH / 4; h4++){
        float4 wq = Q[h4];
        #pragma unroll
        for (int r = 0; r < GR; r++){
            float4 hh = *(const float4*)&hn_s[r][h4 * 4];
            aq[r] += wq.x*hh.x + wq.y*hh.y + wq.z*hh.z + wq.w*hh.w;
        }
    }
    #pragma unroll
    for (int r = 0; r < GR; r++) g_q[(n0 + r) * HH + j] = aq[r];
}

// ---------------- fused k-GEMM (HMMA bf16 split) + step-1 score ----------
// grid (16, 1024): blockIdx.y = n, blockIdx.x = 128-row L-tile.
// 256 threads, 8 warps = 4 m-groups x 2 n-halves; warp tile m32 x n64
// (two m16 subtiles share each B fragment -> 2x less B L1 traffic).
// A via ldmatrix.x4 from smem hi/lo planes (pitch 136 bf16, conflict-free);
// B via LDG.128 uint4 fragments (L1-hot 64 KB). 3 combos hh + hl + lh.
#define APITCH 136
#define SM_AHI 0
#define SM_ALO 34816
#define SM_QS  69632
#define SM_WS  70144
#define SM_PART 70656
#define KQ_SMEM 71680

__global__ void __launch_bounds__(256, 2) kq_kernel(
    const float* __restrict__ eo,
    const float* __restrict__ w_score, const float* __restrict__ q)
{
    extern __shared__ char sm[];
    __nv_bfloat16* Ahi = (__nv_bfloat16*)(sm + SM_AHI);
    __nv_bfloat16* Alo = (__nv_bfloat16*)(sm + SM_ALO);
    float* qs   = (float*)(sm + SM_QS);
    float* ws   = (float*)(sm + SM_WS);
    float* part = (float*)(sm + SM_PART);      // [2][128]

    const int n    = blockIdx.y;
    const int l0   = blockIdx.x * 128;
    const int tid  = threadIdx.x;
    const int wid  = tid >> 5;
    const int lane = tid & 31;
    const int mg   = wid & 3;                  // m-group (32 rows)
    const int nh   = wid >> 2;                 // n-half (64 cols)
    const int g    = lane >> 2;                // quad row
    const int tig  = lane & 3;

    // stage eo tile (128x128 fp32) -> hi/lo bf16 planes
    {
        const float4* src = (const float4*)(eo + ((size_t)n * LL + l0) * HH);
        #pragma unroll
        for (int it = 0; it < 16; it++){
            int idx = tid + it * 256;          // 4096 float4
            int row = idx >> 5;
            int c4  = idx & 31;                // k = 4*c4
            float4 v = src[idx];
            __nv_bfloat16 h0 = __float2bfloat16(v.x);
            __nv_bfloat16 h1 = __float2bfloat16(v.y);
            __nv_bfloat16 h2 = __float2bfloat16(v.z);
            __nv_bfloat16 h3 = __float2bfloat16(v.w);
            __nv_bfloat16 e0 = __float2bfloat16(v.x - __bfloat162float(h0));
            __nv_bfloat16 e1 = __float2bfloat16(v.y - __bfloat162float(h1));
            __nv_bfloat16 e2 = __float2bfloat16(v.z - __bfloat162float(h2));
            __nv_bfloat16 e3 = __float2bfloat16(v.w - __bfloat162float(h3));
            uint2 hv = make_uint2(pack_bf16x2(h0, h1), pack_bf16x2(h2, h3));
            uint2 lv = make_uint2(pack_bf16x2(e0, e1), pack_bf16x2(e2, e3));
            *(uint2*)(Ahi + row * APITCH + c4 * 4) = hv;
            *(uint2*)(Alo + row * APITCH + c4 * 4) = lv;
        }
        if (tid < HH){
            qs[tid] = q[(size_t)n * HH + tid];
            ws[tid] = w_score[tid];
        }
    }
    __syncthreads();

    float acc[2][8][4];                        // [m-subtile][ntile][frag]
    #pragma unroll
    for (int s = 0; s < 2; s++)
        #pragma unroll
        for (int nt = 0; nt < 8; nt++)
            #pragma unroll
            for (int i = 0; i < 4; i++) acc[s][nt][i] = 0.0f;

    const int mgb = mg * 32;
    // ldmatrix x4 lane->address map: lanes 0-7 m0(r, kk), 8-15 m1(r+8, kk),
    // 16-23 m2(r, kk+8), 24-31 m3(r+8, kk+8)
    const int lq   = lane >> 3;
    const int lrow = mgb + (lane & 7) + (lq & 1) * 8;
    const int lcol = (lq >> 1) * 8;
    const uint32_t ahi_b = (uint32_t)__cvta_generic_to_shared(Ahi)
                         + (uint32_t)(lrow * APITCH + lcol) * 2u;
    const uint32_t alo_b = (uint32_t)__cvta_generic_to_shared(Alo)
                         + (uint32_t)(lrow * APITCH + lcol) * 2u;
    const uint32_t sub1 = 16u * APITCH * 2u;   // +16 rows
    const uint4* wb4 = g_Wb4;

    #pragma unroll
    for (int kstep = 0; kstep < 8; kstep++){
        uint32_t ah[2][4], al[2][4];
        ldsm_x4(ah[0][0], ah[0][1], ah[0][2], ah[0][3], ahi_b + kstep * 32u);
        ldsm_x4(al[0][0], al[0][1], al[0][2], al[0][3], alo_b + kstep * 32u);
        ldsm_x4(ah[1][0], ah[1][1], ah[1][2], ah[1][3], ahi_b + sub1 + kstep * 32u);
        ldsm_x4(al[1][0], al[1][1], al[1][2], al[1][3], alo_b + sub1 + kstep * 32u);
        #pragma unroll
        for (int p = 0; p < 4; p++){
            const int pp = nh * 4 + p;                       // global ntpair
            uint4 Bh = wb4[(0 * 8 + kstep) * 256 + pp * 32 + lane];
            uint4 Bl = wb4[(1 * 8 + kstep) * 256 + pp * 32 + lane];
            #pragma unroll
            for (int s = 0; s < 2; s++){
                mma_bf16(acc[s][2*p],   ah[s][0], ah[s][1], ah[s][2], ah[s][3], Bh.x, Bh.y); // hh
                mma_bf16(acc[s][2*p],   ah[s][0], ah[s][1], ah[s][2], ah[s][3], Bl.x, Bl.y); // hl
                mma_bf16(acc[s][2*p],   al[s][0], al[s][1], al[s][2], al[s][3], Bh.x, Bh.y); // lh
                mma_bf16(acc[s][2*p+1], ah[s][0], ah[s][1], ah[s][2], ah[s][3], Bh.z, Bh.w);
                mma_bf16(acc[s][2*p+1], ah[s][0], ah[s][1], ah[s][2], ah[s][3], Bl.z, Bl.w);
                mma_bf16(acc[s][2*p+1], al[s][0], al[s][1], al[s][2], al[s][3], Bh.z, Bh.w);
            }
        }
    }

    // epilogue: store k, fused logits
    #pragma unroll
    for (int s = 0; s < 2; s++){
        const int r0 = mgb + s * 16 + g;
        const int r1 = r0 + 8;
        float s0 = 0.0f, s1 = 0.0f;
        #pragma unroll
        for (int nt = 0; nt < 8; nt++){
            const int c0 = nh * 64 + nt * 8 + 2 * tig;
            float* k0p = g_k + ((size_t)n * LL + l0 + r0) * HH + c0;
            float* k1p = g_k + ((size_t)n * LL + l0 + r1) * HH + c0;
            *(float2*)k0p = make_float2(acc[s][nt][0], acc[s][nt][1]);
            *(float2*)k1p = make_float2(acc[s][nt][2], acc[s][nt][3]);
            const float w0 = ws[c0], w1 = ws[c0 + 1];
            const float q0 = qs[c0], q1 = qs[c0 + 1];
            s0 += w0 * acc_tanh(q0 + acc[s][nt][0]) + w1 * acc_tanh(q1 + acc[s][nt][1]);
            s1 += w0 * acc_tanh(q0 + acc[s][nt][2]) + w1 * acc_tanh(q1 + acc[s][nt][3]);
        }
        // reduce over tig (4 lanes share a row)
        #pragma unroll
        for (int off = 1; off < 4; off <<= 1){
            s0 += __shfl_xor_sync(0xffffffffu, s0, off);
            s1 += __shfl_xor_sync(0xffffffffu, s1, off);
        }
        if (tig == 0){
            part[nh * 128 + r0] = s0;
            part[nh * 128 + r1] = s1;
        }
    }
    __syncthreads();
    if (tid < 128)
        g_logits[(size_t)n * LL + l0 + tid] = part[tid] + part[128 + tid];
}

// ---------------- step-2 score: read k scratch (4 rows per warp) ---------
__global__ void __launch_bounds__(256) score2_kernel(
    const float* __restrict__ w_score, const float* __restrict__ q)
{
    const size_t row0 = (size_t)blockIdx.x * 32 + (threadIdx.x >> 5) * 4;
    const int    lane = threadIdx.x & 31;

    const float4 wv = *(const float4*)(w_score + 4 * lane);
    float4 kv[4];
    #pragma unroll
    for (int r = 0; r < 4; r++)
        kv[r] = *(const float4*)(g_k + (row0 + r) * HH + 4 * lane);

    #pragma unroll
    for (int r = 0; r < 4; r++){
        const int n = (int)((row0 + r) >> 11);
        const float4 qv = *(const float4*)(q + (size_t)n * HH + 4 * lane);
        float s = wv.x * acc_tanh(qv.x + kv[r].x)
                + wv.y * acc_tanh(qv.y + kv[r].y)
                + wv.z * acc_tanh(qv.z + kv[r].z)
                + wv.w * acc_tanh(qv.w + kv[r].w);
        #pragma unroll
        for (int off = 16; off > 0; off >>= 1)
            s += __shfl_xor_sync(0xffffffffu, s, off);
        if (lane == 0) g_logits[row0 + r] = s;
    }
}

// ---------------- softmax + argmax (+ gather next input) ----------------
__global__ void __launch_bounds__(256) softmax_kernel(
    const float* __restrict__ enc_in, float* __restrict__ out,
    int step, int do_gather)
{
    __shared__ float smax[256];
    __shared__ int   sidx[256];
    __shared__ float ssum[256];
    const int n   = blockIdx.x;
    const int tid = threadIdx.x;
    const float* lg = g_logits + (size_t)n * LL;

    float v[8];
    float vmax = -1e30f; int vidx = 0;
    #pragma unroll
    for (int i = 0; i < 8; i++){
        int l = tid + i * 256;
        v[i] = lg[l];
        if (v[i] > vmax){ vmax = v[i]; vidx = l; }
    }
    smax[tid] = vmax; sidx[tid] = vidx;
    __syncthreads();
    for (int s = 128; s > 0; s >>= 1){
        if (tid < s){
            float ov = smax[tid + s]; int oi = sidx[tid + s];
            if (ov > smax[tid] || (ov == smax[tid] && oi < sidx[tid])){
                smax[tid] = ov; sidx[tid] = oi;
            }
        }
        __syncthreads();
    }
    const float m   = smax[0];
    const int   idx = sidx[0];
    __syncthreads();

    float e[8];
    float loc = 0.0f;
    #pragma unroll
    for (int i = 0; i < 8; i++){ e[i] = expf(v[i] - m); loc += e[i]; }
    ssum[tid] = loc;
    __syncthreads();
    for (int s = 128; s > 0; s >>= 1){
        if (tid < s) ssum[tid] += ssum[tid + s];
        __syncthreads();
    }
    const float inv = 1.0f / ssum[0];

    float* orow = out + ((size_t)n * 2 + step) * LL;
    #pragma unroll
    for (int i = 0; i < 8; i++) orow[tid + i * 256] = e[i] * inv;

    if (do_gather && tid < HH)
        g_x[n * HH + tid] = enc_in[((size_t)n * LL + idx) * HH + tid];
}

// ---------------- launch ----------------
extern "C" void kernel_launch(void* const* d_in, const int* in_sizes, int n_in,
                              void* d_out, int out_size)
{
    const float* enc_in  = (const float*)d_in[0];
    const float* enc_out = (const float*)d_in[1];
    const float* state0  = (const float*)d_in[2];
    const float* W_ih    = (const float*)d_in[3];
    const float* W_hh    = (const float*)d_in[4];
    const float* b_ih    = (const float*)d_in[5];
    const float* b_hh    = (const float*)d_in[6];
    const float* Wq      = (const float*)d_in[7];
    const float* Wk      = (const float*)d_in[8];
    const float* w_score = (const float*)d_in[9];
    float* out = (float*)d_out;

    float *p_x, *p_state, *p_q;
    cudaGetSymbolAddress((void**)&p_x, g_x);
    cudaGetSymbolAddress((void**)&p_state, g_state);
    cudaGetSymbolAddress((void**)&p_q, g_q);

    cudaFuncSetAttribute(kq_kernel,
                         cudaFuncAttributeMaxDynamicSharedMemorySize, KQ_SMEM);

    // prologue
    init_x_kernel<<<(NN * HH + 255) / 256, 256>>>();
    build_wb_kernel<<<16, 256>>>(Wk);
    // step 1
    gru_kernel<<<NN / GR, HH>>>(p_x, state0, W_ih, W_hh, b_ih, b_hh, Wq);
    kq_kernel<<<dim3(LL / 128, NN), 256, KQ_SMEM>>>(enc_out, w_score, p_q);
    softmax_kernel<<<NN, 256>>>(enc_in, out, 0, 1);
    // step 2
    gru_kernel<<<NN / GR, HH>>>(p_x, p_state, W_ih, W_hh, b_ih, b_hh, Wq);
    score2_kernel<<<(int)(((size_t)NN * LL) / 32), 256>>>(w_score, p_q);
    softmax_kernel<<<NN, 256>>>(enc_in, out, 1, 0);
}

// round 17
// speedup vs baseline: 3.2679x; 1.0108x over previous
#include <cuda_runtime.h>
#include <cuda_bf16.h>
#include <cstdint>
#include <cstddef>
#include <math.h>

#define NN 1024
#define LL 2048
#define HH 128

// ---------------- scratch (device globals; no allocation) ----------------
static __device__ float g_k[(size_t)NN * LL * HH];   // 1 GiB
static __device__ float g_logits[(size_t)NN * LL];
static __device__ float g_x[NN * HH];
static __device__ float g_state[NN * HH];
static __device__ float g_q[NN * HH];
// Wk as pre-swizzled bf16 b-fragments, uint4-packed (2 n-tiles per entry):
// idx4 = ((plane*8 + kstep)*8 + ntpair)*32 + lane
// o(nt) = nt*8 + lane/4, k0 = kstep*16 + 2*(lane%4), k1 = k0 + 8
// plane 0 = hi bf16, plane 1 = lo residual
static __device__ uint4 g_Wb4[4096];

// ---------------- math helpers ----------------
__device__ __forceinline__ float ex2f(float x){ float r; asm("ex2.approx.f32 %0, %1;" : "=f"(r) : "f"(x)); return r; }
__device__ __forceinline__ float rcpaf(float x){ float r; asm("rcp.approx.f32 %0, %1;" : "=f"(r) : "f"(x)); return r; }

// tanh(x) = 1 - 2/(1+e^{2x}); ex2 + rcp + one Newton step  (~1e-7 abs err)
__device__ __forceinline__ float acc_tanh(float x){
    float y = fminf(x * 2.8853900817779268f, 80.0f);   // 2/ln(2)
    float e = ex2f(y);
    float d = e + 1.0f;
    float r = rcpaf(d);
    r = r * fmaf(-d, r, 2.0f);                         // Newton
    return fmaf(-2.0f, r, 1.0f);
}

__device__ __forceinline__ void mma_bf16(float* c,
    uint32_t a0, uint32_t a1, uint32_t a2, uint32_t a3,
    uint32_t b0, uint32_t b1)
{
    asm volatile(
        "mma.sync.aligned.m16n8k16.row.col.f32.bf16.bf16.f32 "
        "{%0,%1,%2,%3}, {%4,%5,%6,%7}, {%8,%9}, {%0,%1,%2,%3};"
        : "+f"(c[0]), "+f"(c[1]), "+f"(c[2]), "+f"(c[3])
        : "r"(a0), "r"(a1), "r"(a2), "r"(a3), "r"(b0), "r"(b1));
}

__device__ __forceinline__ void ldsm_x4(uint32_t& r0, uint32_t& r1,
                                        uint32_t& r2, uint32_t& r3, uint32_t addr)
{
    asm volatile("ldmatrix.sync.aligned.m8n8.x4.shared.b16 {%0,%1,%2,%3}, [%4];"
        : "=r"(r0), "=r"(r1), "=r"(r2), "=r"(r3) : "r"(addr));
}

__device__ __forceinline__ uint32_t pack_bf16x2(__nv_bfloat16 lo, __nv_bfloat16 hi16){
    return (uint32_t)__bfloat16_as_ushort(lo) | ((uint32_t)__bfloat16_as_ushort(hi16) << 16);
}

// ---------------- build swizzled bf16 B fragments (once per replay) ------
__global__ void __launch_bounds__(256) build_wb_kernel(const float* __restrict__ Wk){
    int e = blockIdx.x * 256 + threadIdx.x;       // 16 blocks -> 4096
    int lane  = e & 31;
    int pp    = (e >> 5) & 7;                     // ntpair
    int kstep = (e >> 8) & 7;
    int plane = (e >> 11) & 1;
    int o0 = (2 * pp) * 8 + (lane >> 2);
    int o1 = o0 + 8;
    int k0 = kstep * 16 + 2 * (lane & 3);
    int k1 = k0 + 8;

    auto cv = [&](int o, int k) -> __nv_bfloat16 {
        float x = Wk[o * HH + k];
        __nv_bfloat16 h = __float2bfloat16(x);
        if (plane == 0) return h;
        return __float2bfloat16(x - __bfloat162float(h));
    };
    uint4 v;
    v.x = pack_bf16x2(cv(o0, k0), cv(o0, k0 + 1));
    v.y = pack_bf16x2(cv(o0, k1), cv(o0, k1 + 1));
    v.z = pack_bf16x2(cv(o1, k0), cv(o1, k0 + 1));
    v.w = pack_bf16x2(cv(o1, k1), cv(o1, k1 + 1));
    g_Wb4[e] = v;
}

// ---------------- GRU cell + q projection ----------------
// x_ones: step-1 decoder input is all-ones; skip the x load entirely.
#define GR 8
__global__ void __launch_bounds__(HH) gru_kernel(
    const float* __restrict__ x_in, const float* __restrict__ h_in,
    const float* __restrict__ W_ih, const float* __restrict__ W_hh,
    const float* __restrict__ b_ih, const float* __restrict__ b_hh,
    const float* __restrict__ Wq, int x_ones)
{
    __shared__ float x_s[GR][HH];
    __shared__ float h_s[GR][HH];
    __shared__ float hn_s[GR][HH];
    const int n0 = blockIdx.x * GR;
    const int j  = threadIdx.x;
    for (int r = 0; r < GR; r++){
        x_s[r][j] = x_ones ? 1.0f : x_in[(n0 + r) * HH + j];
        h_s[r][j] = h_in[(n0 + r) * HH + j];
    }
    __syncthreads();

    float ar[GR], az[GR], anx[GR], anh[GR];
    #pragma unroll
    for (int r = 0; r < GR; r++){ ar[r] = az[r] = anx[r] = anh[r] = 0.0f; }

    const float4* Wr = (const float4*)(W_ih + (size_t)j * HH);
    const float4* Wz = (const float4*)(W_ih + (size_t)(HH + j) * HH);
    const float4* Wn = (const float4*)(W_ih + (size_t)(2 * HH + j) * HH);
    const float4* Vr = (const float4*)(W_hh + (size_t)j * HH);
    const float4* Vz = (const float4*)(W_hh + (size_t)(HH + j) * HH);
    const float4* Vn = (const float4*)(W_hh + (size_t)(2 * HH + j) * HH);

    for (int h4 = 0; h4 < HH / 4; h4++){
        float4 wr = Wr[h4], wz = Wz[h4], wn = Wn[h4];
        float4 vr = Vr[h4], vz = Vz[h4], vn = Vn[h4];
        #pragma unroll
        for (int r = 0; r < GR; r++){
            float4 xx = *(const float4*)&x_s[r][h4 * 4];
            float4 hh = *(const float4*)&h_s[r][h4 * 4];
            ar[r]  += wr.x*xx.x + wr.y*xx.y + wr.z*xx.z + wr.w*xx.w
                    + vr.x*hh.x + vr.y*hh.y + vr.z*hh.z + vr.w*hh.w;
            az[r]  += wz.x*xx.x + wz.y*xx.y + wz.z*xx.z + wz.w*xx.w
                    + vz.x*hh.x + vz.y*hh.y + vz.z*hh.z + vz.w*hh.w;
            anx[r] += wn.x*xx.x + wn.y*xx.y + wn.z*xx.z + wn.w*xx.w;
            anh[r] += vn.x*hh.x + vn.y*hh.y + vn.z*hh.z + vn.w*hh.w;
        }
    }
    const float br  = b_ih[j] + b_hh[j];
    const float bz  = b_ih[HH + j] + b_hh[HH + j];
    const float bnx = b_ih[2 * HH + j];
    const float bnh = b_hh[2 * HH + j];
    #pragma unroll
    for (int r = 0; r < GR; r++){
        float rr = 1.0f / (1.0f + expf(-(ar[r] + br)));
        float zz = 1.0f / (1.0f + expf(-(az[r] + bz)));
        float nn = tanhf(anx[r] + bnx + rr * (anh[r] + bnh));
        float hp = (1.0f - zz) * nn + zz * h_s[r][j];
        hn_s[r][j] = hp;
        g_state[(n0 + r) * HH + j] = hp;
    }
    __syncthreads();
    float aq[GR];
    #pragma unroll
    for (int r = 0; r < GR; r++) aq[r] = 0.0f;
    const float4* Q = (const float4*)(Wq + (size_t)j * HH);
    for (int h4 = 0; h4 < HH / 4; h4++){
        float4 wq = Q[h4];
        #pragma unroll
        for (int r = 0; r < GR; r++){
            float4 hh = *(const float4*)&hn_s[r][h4 * 4];
            aq[r] += wq.x*hh.x + wq.y*hh.y + wq.z*hh.z + wq.w*hh.w;
        }
    }
    #pragma unroll
    for (int r = 0; r < GR; r++) g_q[(n0 + r) * HH + j] = aq[r];
}

// ---------------- fused k-GEMM (HMMA bf16 split) + step-1 score ----------
// grid (16, 1024): blockIdx.y = n, blockIdx.x = 128-row L-tile.
// 256 threads, 8 warps = 4 m-groups x 2 n-halves; warp tile m32 x n64.
// Combo-major MMA order: hh x4 accs, hl x4, lh x4 -> RAW gap 4 per acc.
#define APITCH 136
#define SM_AHI 0
#define SM_ALO 34816
#define SM_QS  69632
#define SM_WS  70144
#define SM_PART 70656
#define KQ_SMEM 71680

__global__ void __launch_bounds__(256, 2) kq_kernel(
    const float* __restrict__ eo,
    const float* __restrict__ w_score, const float* __restrict__ q)
{
    extern __shared__ char sm[];
    __nv_bfloat16* Ahi = (__nv_bfloat16*)(sm + SM_AHI);
    __nv_bfloat16* Alo = (__nv_bfloat16*)(sm + SM_ALO);
    float* qs   = (float*)(sm + SM_QS);
    float* ws   = (float*)(sm + SM_WS);
    float* part = (float*)(sm + SM_PART);      // [2][128]

    const int n    = blockIdx.y;
    const int l0   = blockIdx.x * 128;
    const int tid  = threadIdx.x;
    const int wid  = tid >> 5;
    const int lane = tid & 31;
    const int mg   = wid & 3;                  // m-group (32 rows)
    const int nh   = wid >> 2;                 // n-half (64 cols)
    const int g    = lane >> 2;                // quad row
    const int tig  = lane & 3;

    // stage eo tile (128x128 fp32) -> hi/lo bf16 planes (STS.128)
    {
        const float4* src = (const float4*)(eo + ((size_t)n * LL + l0) * HH);
        #pragma unroll
        for (int it = 0; it < 8; it++){
            int idx2 = tid + it * 256;         // 2048 float4-pairs
            int row  = idx2 >> 4;              // 16 pairs per row
            int c8   = idx2 & 15;              // 8-float chunk
            float4 v0 = src[idx2 * 2];
            float4 v1 = src[idx2 * 2 + 1];
            __nv_bfloat16 h0 = __float2bfloat16(v0.x), h1 = __float2bfloat16(v0.y);
            __nv_bfloat16 h2 = __float2bfloat16(v0.z), h3 = __float2bfloat16(v0.w);
            __nv_bfloat16 h4 = __float2bfloat16(v1.x), h5 = __float2bfloat16(v1.y);
            __nv_bfloat16 h6 = __float2bfloat16(v1.z), h7 = __float2bfloat16(v1.w);
            uint4 hv, lv;
            hv.x = pack_bf16x2(h0, h1); hv.y = pack_bf16x2(h2, h3);
            hv.z = pack_bf16x2(h4, h5); hv.w = pack_bf16x2(h6, h7);
            lv.x = pack_bf16x2(__float2bfloat16(v0.x - __bfloat162float(h0)),
                               __float2bfloat16(v0.y - __bfloat162float(h1)));
            lv.y = pack_bf16x2(__float2bfloat16(v0.z - __bfloat162float(h2)),
                               __float2bfloat16(v0.w - __bfloat162float(h3)));
            lv.z = pack_bf16x2(__float2bfloat16(v1.x - __bfloat162float(h4)),
                               __float2bfloat16(v1.y - __bfloat162float(h5)));
            lv.w = pack_bf16x2(__float2bfloat16(v1.z - __bfloat162float(h6)),
                               __float2bfloat16(v1.w - __bfloat162float(h7)));
            *(uint4*)(Ahi + row * APITCH + c8 * 8) = hv;
            *(uint4*)(Alo + row * APITCH + c8 * 8) = lv;
        }
        if (tid < HH){
            qs[tid] = q[(size_t)n * HH + tid];
            ws[tid] = w_score[tid];
        }
    }
    __syncthreads();

    float acc[2][8][4];                        // [m-subtile][ntile][frag]
    #pragma unroll
    for (int s = 0; s < 2; s++)
        #pragma unroll
        for (int nt = 0; nt < 8; nt++)
            #pragma unroll
            for (int i = 0; i < 4; i++) acc[s][nt][i] = 0.0f;

    const int mgb = mg * 32;
    // ldmatrix x4 lane->address map: lanes 0-7 m0(r, kk), 8-15 m1(r+8, kk),
    // 16-23 m2(r, kk+8), 24-31 m3(r+8, kk+8)
    const int lq   = lane >> 3;
    const int lrow = mgb + (lane & 7) + (lq & 1) * 8;
    const int lcol = (lq >> 1) * 8;
    const uint32_t ahi_b = (uint32_t)__cvta_generic_to_shared(Ahi)
                         + (uint32_t)(lrow * APITCH + lcol) * 2u;
    const uint32_t alo_b = (uint32_t)__cvta_generic_to_shared(Alo)
                         + (uint32_t)(lrow * APITCH + lcol) * 2u;
    const uint32_t sub1 = 16u * APITCH * 2u;   // +16 rows
    const uint4* wb4 = g_Wb4;

    #pragma unroll
    for (int kstep = 0; kstep < 8; kstep++){
        uint32_t ah[2][4], al[2][4];
        ldsm_x4(ah[0][0], ah[0][1], ah[0][2], ah[0][3], ahi_b + kstep * 32u);
        ldsm_x4(ah[1][0], ah[1][1], ah[1][2], ah[1][3], ahi_b + sub1 + kstep * 32u);
        ldsm_x4(al[0][0], al[0][1], al[0][2], al[0][3], alo_b + kstep * 32u);
        ldsm_x4(al[1][0], al[1][1], al[1][2], al[1][3], alo_b + sub1 + kstep * 32u);
        #pragma unroll
        for (int p = 0; p < 4; p++){
            const int pp = nh * 4 + p;                       // global ntpair
            uint4 Bh = wb4[(0 * 8 + kstep) * 256 + pp * 32 + lane];
            uint4 Bl = wb4[(1 * 8 + kstep) * 256 + pp * 32 + lane];
            // hh round: 4 independent accumulators
            mma_bf16(acc[0][2*p],   ah[0][0], ah[0][1], ah[0][2], ah[0][3], Bh.x, Bh.y);
            mma_bf16(acc[1][2*p],   ah[1][0], ah[1][1], ah[1][2], ah[1][3], Bh.x, Bh.y);
            mma_bf16(acc[0][2*p+1], ah[0][0], ah[0][1], ah[0][2], ah[0][3], Bh.z, Bh.w);
            mma_bf16(acc[1][2*p+1], ah[1][0], ah[1][1], ah[1][2], ah[1][3], Bh.z, Bh.w);
            // hl round
            mma_bf16(acc[0][2*p],   ah[0][0], ah[0][1], ah[0][2], ah[0][3], Bl.x, Bl.y);
            mma_bf16(acc[1][2*p],   ah[1][0], ah[1][1], ah[1][2], ah[1][3], Bl.x, Bl.y);
            mma_bf16(acc[0][2*p+1], ah[0][0], ah[0][1], ah[0][2], ah[0][3], Bl.z, Bl.w);
            mma_bf16(acc[1][2*p+1], ah[1][0], ah[1][1], ah[1][2], ah[1][3], Bl.z, Bl.w);
            // lh round
            mma_bf16(acc[0][2*p],   al[0][0], al[0][1], al[0][2], al[0][3], Bh.x, Bh.y);
            mma_bf16(acc[1][2*p],   al[1][0], al[1][1], al[1][2], al[1][3], Bh.x, Bh.y);
            mma_bf16(acc[0][2*p+1], al[0][0], al[0][1], al[0][2], al[0][3], Bh.z, Bh.w);
            mma_bf16(acc[1][2*p+1], al[1][0], al[1][1], al[1][2], al[1][3], Bh.z, Bh.w);
        }
    }

    // epilogue: store k, fused logits
    #pragma unroll
    for (int s = 0; s < 2; s++){
        const int r0 = mgb + s * 16 + g;
        const int r1 = r0 + 8;
        float s0 = 0.0f, s1 = 0.0f;
        #pragma unroll
        for (int nt = 0; nt < 8; nt++){
            const int c0 = nh * 64 + nt * 8 + 2 * tig;
            float* k0p = g_k + ((size_t)n * LL + l0 + r0) * HH + c0;
            float* k1p = g_k + ((size_t)n * LL + l0 + r1) * HH + c0;
            *(float2*)k0p = make_float2(acc[s][nt][0], acc[s][nt][1]);
            *(float2*)k1p = make_float2(acc[s][nt][2], acc[s][nt][3]);
            const float w0 = ws[c0], w1 = ws[c0 + 1];
            const float q0 = qs[c0], q1 = qs[c0 + 1];
            s0 += w0 * acc_tanh(q0 + acc[s][nt][0]) + w1 * acc_tanh(q1 + acc[s][nt][1]);
            s1 += w0 * acc_tanh(q0 + acc[s][nt][2]) + w1 * acc_tanh(q1 + acc[s][nt][3]);
        }
        // reduce over tig (4 lanes share a row)
        #pragma unroll
        for (int off = 1; off < 4; off <<= 1){
            s0 += __shfl_xor_sync(0xffffffffu, s0, off);
            s1 += __shfl_xor_sync(0xffffffffu, s1, off);
        }
        if (tig == 0){
            part[nh * 128 + r0] = s0;
            part[nh * 128 + r1] = s1;
        }
    }
    __syncthreads();
    if (tid < 128)
        g_logits[(size_t)n * LL + l0 + tid] = part[tid] + part[128 + tid];
}

// ---------------- step-2 score: read k scratch (8 rows per warp) ---------
__global__ void __launch_bounds__(256) score2_kernel(
    const float* __restrict__ w_score, const float* __restrict__ q)
{
    const size_t row0 = (size_t)blockIdx.x * 64 + (threadIdx.x >> 5) * 8;
    const int    lane = threadIdx.x & 31;

    const float4 wv = *(const float4*)(w_score + 4 * lane);
    float4 kv[8];
    #pragma unroll
    for (int r = 0; r < 8; r++)
        kv[r] = *(const float4*)(g_k + (row0 + r) * HH + 4 * lane);

    #pragma unroll
    for (int r = 0; r < 8; r++){
        const int n = (int)((row0 + r) >> 11);
        const float4 qv = *(const float4*)(q + (size_t)n * HH + 4 * lane);
        float s = wv.x * acc_tanh(qv.x + kv[r].x)
                + wv.y * acc_tanh(qv.y + kv[r].y)
                + wv.z * acc_tanh(qv.z + kv[r].z)
                + wv.w * acc_tanh(qv.w + kv[r].w);
        #pragma unroll
        for (int off = 16; off > 0; off >>= 1)
            s += __shfl_xor_sync(0xffffffffu, s, off);
        if (lane == 0) g_logits[row0 + r] = s;
    }
}

// ---------------- softmax + argmax (+ gather next input) ----------------
__global__ void __launch_bounds__(256) softmax_kernel(
    const float* __restrict__ enc_in, float* __restrict__ out,
    int step, int do_gather)
{
    __shared__ float smax[256];
    __shared__ int   sidx[256];
    __shared__ float ssum[256];
    const int n   = blockIdx.x;
    const int tid = threadIdx.x;
    const float* lg = g_logits + (size_t)n * LL;

    float v[8];
    float vmax = -1e30f; int vidx = 0;
    #pragma unroll
    for (int i = 0; i < 8; i++){
        int l = tid + i * 256;
        v[i] = lg[l];
        if (v[i] > vmax){ vmax = v[i]; vidx = l; }
    }
    smax[tid] = vmax; sidx[tid] = vidx;
    __syncthreads();
    for (int s = 128; s > 0; s >>= 1){
        if (tid < s){
            float ov = smax[tid + s]; int oi = sidx[tid + s];
            if (ov > smax[tid] || (ov == smax[tid] && oi < sidx[tid])){
                smax[tid] = ov; sidx[tid] = oi;
            }
        }
        __syncthreads();
    }
    const float m   = smax[0];
    const int   idx = sidx[0];
    __syncthreads();

    float e[8];
    float loc = 0.0f;
    #pragma unroll
    for (int i = 0; i < 8; i++){ e[i] = expf(v[i] - m); loc += e[i]; }
    ssum[tid] = loc;
    __syncthreads();
    for (int s = 128; s > 0; s >>= 1){
        if (tid < s) ssum[tid] += ssum[tid + s];
        __syncthreads();
    }
    const float inv = 1.0f / ssum[0];

    float* orow = out + ((size_t)n * 2 + step) * LL;
    #pragma unroll
    for (int i = 0; i < 8; i++) orow[tid + i * 256] = e[i] * inv;

    if (do_gather && tid < HH)
        g_x[n * HH + tid] = enc_in[((size_t)n * LL + idx) * HH + tid];
}

// ---------------- launch ----------------
extern "C" void kernel_launch(void* const* d_in, const int* in_sizes, int n_in,
                              void* d_out, int out_size)
{
    const float* enc_in  = (const float*)d_in[0];
    const float* enc_out = (const float*)d_in[1];
    const float* state0  = (const float*)d_in[2];
    const float* W_ih    = (const float*)d_in[3];
    const float* W_hh    = (const float*)d_in[4];
    const float* b_ih    = (const float*)d_in[5];
    const float* b_hh    = (const float*)d_in[6];
    const float* Wq      = (const float*)d_in[7];
    const float* Wk      = (const float*)d_in[8];
    const float* w_score = (const float*)d_in[9];
    float* out = (float*)d_out;

    float *p_x, *p_state, *p_q;
    cudaGetSymbolAddress((void**)&p_x, g_x);
    cudaGetSymbolAddress((void**)&p_state, g_state);
    cudaGetSymbolAddress((void**)&p_q, g_q);

    cudaFuncSetAttribute(kq_kernel,
                         cudaFuncAttributeMaxDynamicSharedMemorySize, KQ_SMEM);

    // prologue
    build_wb_kernel<<<16, 256>>>(Wk);
    // step 1 (decoder input = ones; no init kernel needed)
    gru_kernel<<<NN / GR, HH>>>(p_x, state0, W_ih, W_hh, b_ih, b_hh, Wq, 1);
    kq_kernel<<<dim3(LL / 128, NN), 256, KQ_SMEM>>>(enc_out, w_score, p_q);
    softmax_kernel<<<NN, 256>>>(enc_in, out, 0, 1);
    // step 2
    gru_kernel<<<NN / GR, HH>>>(p_x, p_state, W_ih, W_hh, b_ih, b_hh, Wq, 0);
    score2_kernel<<<(int)(((size_t)NN * LL) / 64), 256>>>(w_score, p_q);
    softmax_kernel<<<NN, 256>>>(enc_in, out, 1, 0);
}